// round 4
// baseline (speedup 1.0000x reference)
#include <cuda_runtime.h>
#include <math.h>

// Problem constants (fixed shapes from reference)
#define NB    4        // batches
#define NN    5000     // nodes
#define SEQ   128      // input features
#define NOUT  128      // output features
#define NE    80000    // edges
#define MROWS (NB*NN)  // 20000
#define MPAD  20096    // 157 * 128, padded row count for GEMM
#define KC    384      // concat feature dim: [X | Txo | Txi]
#define NC    256      // stacked gate outputs: [z | h]

// -------- device scratch (static: no runtime allocation) --------
__device__ __align__(16) float g_Mcat[(size_t)MPAD * KC];   // ~30.9 MB
__device__ __align__(16) float g_D[(size_t)MPAD * NC];      // ~20.6 MB
__device__ __align__(16) float g_Wcat[KC * NC];             // 384 KB
__device__ __align__(16) float g_bias[NC];
__device__ float g_deg[2 * NN];    // [deg_out | deg_in]
__device__ float g_coef[2 * NE];   // [coef_o | coef_i]

// -------- kernel 1: zero degrees --------
__global__ void k_zero_deg() {
    int i = blockIdx.x * blockDim.x + threadIdx.x;
    if (i < 2 * NN) g_deg[i] = 0.0f;
}

// -------- kernel 2: weighted degrees --------
__global__ void k_deg(const int* __restrict__ ei, const float* __restrict__ ew) {
    int e = blockIdx.x * blockDim.x + threadIdx.x;
    if (e >= NE) return;
    float w = ew[e];
    atomicAdd(&g_deg[ei[e]], w);            // deg_out[src]
    atomicAdd(&g_deg[NN + ei[NE + e]], w);  // deg_in[dst]
}

// -------- kernel 3: per-edge coefficients --------
__global__ void k_coef(const int* __restrict__ ei, const float* __restrict__ ew) {
    int e = blockIdx.x * blockDim.x + threadIdx.x;
    if (e >= NE) return;
    float w = ew[e];
    float dо = g_deg[ei[e]];
    float di = g_deg[NN + ei[NE + e]];
    g_coef[e]      = (dо > 0.0f) ? w / dо : 0.0f;  // coef_o
    g_coef[NE + e] = (di > 0.0f) ? w / di : 0.0f;  // coef_i
}

// -------- kernel 4: init Mcat = [X | 0 | 0], pad rows zero --------
__global__ void k_init(const float* __restrict__ x) {
    int idx = blockIdx.x * blockDim.x + threadIdx.x;   // float4 index
    if (idx >= MPAD * (KC / 4)) return;
    int r  = idx / (KC / 4);
    int c4 = idx % (KC / 4);
    float4 v = make_float4(0.f, 0.f, 0.f, 0.f);
    if (c4 < 32 && r < MROWS)
        v = reinterpret_cast<const float4*>(x)[r * 32 + c4];
    reinterpret_cast<float4*>(g_Mcat)[idx] = v;
}

// -------- kernel 5: sparse diffusion scatter --------
// One warp per (edge, batch). Lane l handles 4 contiguous features.
// Txo[dst] += coef_o * X[src];  Txi[src] += coef_i * X[dst].
__device__ __forceinline__ void red2(float* p, float a, float b) {
    asm volatile("red.global.add.v2.f32 [%0], {%1, %2};"
                 :: "l"(p), "f"(a), "f"(b) : "memory");
}

__global__ void k_scatter(const int* __restrict__ ei, const float* __restrict__ x) {
    int gw = (blockIdx.x * blockDim.x + threadIdx.x) >> 5;  // global warp id
    int lane = threadIdx.x & 31;
    if (gw >= NE * NB) return;
    int e = gw % NE;
    int b = gw / NE;
    int se = ei[e];
    int de = ei[NE + e];
    float co = g_coef[e];
    float ci = g_coef[NE + e];

    const float4* xs4 = reinterpret_cast<const float4*>(x + (size_t)(b * NN + se) * SEQ);
    const float4* xd4 = reinterpret_cast<const float4*>(x + (size_t)(b * NN + de) * SEQ);
    float4 xs = xs4[lane];
    float4 xd = xd4[lane];

    float* po = &g_Mcat[(size_t)(b * NN + de) * KC + 128 + lane * 4];  // Txo block
    float* pi = &g_Mcat[(size_t)(b * NN + se) * KC + 256 + lane * 4];  // Txi block
    red2(po,     co * xs.x, co * xs.y);
    red2(po + 2, co * xs.z, co * xs.w);
    red2(pi,     ci * xd.x, ci * xd.y);
    red2(pi + 2, ci * xd.z, ci * xd.w);
}

// -------- kernel 6: build stacked weights Wcat[384,256] + bias --------
// col j<128: z-gate (Wz); j>=128: h-gate (Wh).
// row k<128:  W[0,0][k]+W[1,0][k]   (identity terms, first half only since Xc[:,128:]=0)
// 128<=k<256: W[0,1][k-128]         (forward diffusion)
// 256<=k:     W[1,1][k-256]         (reverse diffusion)
__global__ void k_weights(const float* __restrict__ Wz, const float* __restrict__ bz,
                          const float* __restrict__ Wh, const float* __restrict__ bh) {
    int id = blockIdx.x * blockDim.x + threadIdx.x;
    if (id >= KC * NC) return;
    int k = id / NC;
    int j = id % NC;
    const float* W = (j < 128) ? Wz : Wh;
    int jc = j & 127;
    float v;
    if (k < 128) {
        // W[0][0][k][jc] + W[1][0][k][jc]
        v = W[(0 * 256 + k) * 128 + jc] + W[(2 * 256 + k) * 128 + jc];
    } else if (k < 256) {
        // W[0][1][k-128][jc]
        v = W[(1 * 256 + (k - 128)) * 128 + jc];
    } else {
        // W[1][1][k-256][jc]
        v = W[(3 * 256 + (k - 256)) * 128 + jc];
    }
    g_Wcat[k * NC + j] = v;
    if (id < NC) g_bias[id] = (id < 128) ? bz[id] : bh[id - 128];
}

// -------- kernel 7: SGEMM  D[MPAD,256] = Mcat[MPAD,384] @ Wcat[384,256] + bias --------
#define BM 128
#define BN 128
#define BK 16
__global__ void __launch_bounds__(256) k_gemm() {
    __shared__ float As[BK][BM];   // A transposed in smem
    __shared__ float Bs[BK][BN];
    int bm = blockIdx.x * BM;
    int bn = blockIdx.y * BN;
    int tid = threadIdx.x;
    int tx = tid & 15;       // 0..15 -> 8 output cols each
    int ty = tid >> 4;       // 0..15 -> 8 output rows each

    float acc[8][8];
    #pragma unroll
    for (int i = 0; i < 8; i++)
        #pragma unroll
        for (int j = 0; j < 8; j++) acc[i][j] = 0.f;

    for (int k0 = 0; k0 < KC; k0 += BK) {
        // load A tile 128x16 (512 float4), transpose into As[k][m]
        #pragma unroll
        for (int i = 0; i < 2; i++) {
            int s   = tid + i * 256;       // 0..511
            int row = s >> 2;              // 0..127
            int kq  = (s & 3) * 4;         // 0,4,8,12
            float4 v = *reinterpret_cast<const float4*>(
                &g_Mcat[(size_t)(bm + row) * KC + k0 + kq]);
            As[kq + 0][row] = v.x;
            As[kq + 1][row] = v.y;
            As[kq + 2][row] = v.z;
            As[kq + 3][row] = v.w;
        }
        // load B tile 16x128 (512 float4)
        #pragma unroll
        for (int i = 0; i < 2; i++) {
            int s    = tid + i * 256;
            int krow = s >> 5;             // 0..15
            int cq   = (s & 31) * 4;       // 0..124
            *reinterpret_cast<float4*>(&Bs[krow][cq]) =
                *reinterpret_cast<const float4*>(&g_Wcat[(k0 + krow) * NC + bn + cq]);
        }
        __syncthreads();

        #pragma unroll
        for (int k = 0; k < BK; k++) {
            float a[8], b[8];
            *reinterpret_cast<float4*>(a)     = *reinterpret_cast<float4*>(&As[k][ty * 8]);
            *reinterpret_cast<float4*>(a + 4) = *reinterpret_cast<float4*>(&As[k][ty * 8 + 4]);
            *reinterpret_cast<float4*>(b)     = *reinterpret_cast<float4*>(&Bs[k][tx * 8]);
            *reinterpret_cast<float4*>(b + 4) = *reinterpret_cast<float4*>(&Bs[k][tx * 8 + 4]);
            #pragma unroll
            for (int i = 0; i < 8; i++)
                #pragma unroll
                for (int j = 0; j < 8; j++)
                    acc[i][j] = fmaf(a[i], b[j], acc[i][j]);
        }
        __syncthreads();
    }

    // epilogue: add bias, store
    #pragma unroll
    for (int i = 0; i < 8; i++) {
        int row = bm + ty * 8 + i;
        float* dptr = &g_D[(size_t)row * NC + bn + tx * 8];
        #pragma unroll
        for (int j = 0; j < 8; j += 4) {
            float4 v;
            v.x = acc[i][j + 0] + g_bias[bn + tx * 8 + j + 0];
            v.y = acc[i][j + 1] + g_bias[bn + tx * 8 + j + 1];
            v.z = acc[i][j + 2] + g_bias[bn + tx * 8 + j + 2];
            v.w = acc[i][j + 3] + g_bias[bn + tx * 8 + j + 3];
            *reinterpret_cast<float4*>(dptr + j) = v;
        }
    }
}

// -------- kernel 8: out = (1 - sigmoid(Dz)) * tanh(Dh) --------
__global__ void k_epi(float* __restrict__ out) {
    int idx = blockIdx.x * blockDim.x + threadIdx.x;  // float4 index over [MROWS,128]
    if (idx >= MROWS * 32) return;
    int r  = idx / 32;
    int c4 = idx % 32;
    float4 dz = reinterpret_cast<const float4*>(g_D)[r * 64 + c4];
    float4 dh = reinterpret_cast<const float4*>(g_D)[r * 64 + 32 + c4];
    float4 o;
    // 1 - sigmoid(z) = 1/(1+exp(z))
    o.x = (1.0f / (1.0f + expf(dz.x))) * tanhf(dh.x);
    o.y = (1.0f / (1.0f + expf(dz.y))) * tanhf(dh.y);
    o.z = (1.0f / (1.0f + expf(dz.z))) * tanhf(dh.z);
    o.w = (1.0f / (1.0f + expf(dz.w))) * tanhf(dh.w);
    reinterpret_cast<float4*>(out)[idx] = o;
}

extern "C" void kernel_launch(void* const* d_in, const int* in_sizes, int n_in,
                              void* d_out, int out_size) {
    const float* x  = (const float*)d_in[0];
    const int*   ei = (const int*)d_in[1];
    const float* ew = (const float*)d_in[2];
    const float* Wz = (const float*)d_in[3];
    const float* bz = (const float*)d_in[4];
    // d_in[5] = Wr, d_in[6] = br : mathematically dead (H0 == 0)
    const float* Wh = (const float*)d_in[7];
    const float* bh = (const float*)d_in[8];
    float* out = (float*)d_out;

    k_zero_deg<<<(2 * NN + 255) / 256, 256>>>();
    k_deg<<<(NE + 255) / 256, 256>>>(ei, ew);
    k_coef<<<(NE + 255) / 256, 256>>>(ei, ew);
    k_init<<<(MPAD * (KC / 4) + 255) / 256, 256>>>(x);
    k_weights<<<(KC * NC + 255) / 256, 256>>>(Wz, bz, Wh, bh);
    // scatter: one warp per (edge,batch) -> NE*NB warps, 8 warps/block
    k_scatter<<<(NE * NB + 7) / 8, 256>>>(ei, x);
    dim3 gg(MPAD / BM, NC / BN);
    k_gemm<<<gg, 256>>>();
    k_epi<<<(MROWS * 32 + 255) / 256, 256>>>(out);
}

// round 5
// speedup vs baseline: 1.3584x; 1.3584x over previous
#include <cuda_runtime.h>
#include <math.h>

// Problem constants (fixed shapes)
#define NB    4
#define NN    5000
#define SEQ   128
#define NE    80000
#define MROWS (NB*NN)   // 20000
#define MPAD  20096     // 314*64
#define KC    384       // [X | Txo | Txi]
#define NC    256       // [z | h]
#define SCAN_N (2*NN)   // 10000 combined degree slots (in | out)

// -------- device scratch (static) --------
__device__ __align__(16) float g_Mcat[(size_t)MPAD * KC];   // ~30.9 MB
__device__ __align__(16) float g_Wcat[KC * NC];
__device__ __align__(16) float g_bias[NC];
__device__ float g_deg[2 * NN];       // [deg_out | deg_in] (weighted)
__device__ float g_coef[2 * NE];      // [coef_o | coef_i]
__device__ int   g_cnt[SCAN_N];       // [in-degree | out-degree] (counts)
__device__ int   g_off[SCAN_N + 1];   // CSR offsets (combined: in then out)
__device__ int   g_cursor[SCAN_N];    // fill cursors
__device__ int   g_adj_nbr[2 * NE];   // neighbor per CSR slot
__device__ float g_adj_coef[2 * NE];  // coefficient per CSR slot

// -------- k1: zero degrees + counts --------
__global__ void k_zero() {
    int i = blockIdx.x * blockDim.x + threadIdx.x;
    if (i < 2 * NN) { g_deg[i] = 0.0f; g_cnt[i] = 0; }
}

// -------- k2: weighted degrees + structural counts --------
__global__ void k_degcnt(const int* __restrict__ ei, const float* __restrict__ ew) {
    int e = blockIdx.x * blockDim.x + threadIdx.x;
    if (e >= NE) return;
    int s = ei[e], d = ei[NE + e];
    float w = ew[e];
    atomicAdd(&g_deg[s], w);          // deg_out[src]
    atomicAdd(&g_deg[NN + d], w);     // deg_in[dst]
    atomicAdd(&g_cnt[d], 1);          // in-count of dst  (for Txo CSR)
    atomicAdd(&g_cnt[NN + s], 1);     // out-count of src (for Txi CSR)
}

// -------- k3: per-edge normalization coefficients --------
__global__ void k_coef(const int* __restrict__ ei, const float* __restrict__ ew) {
    int e = blockIdx.x * blockDim.x + threadIdx.x;
    if (e >= NE) return;
    float w = ew[e];
    float dout = g_deg[ei[e]];
    float din  = g_deg[NN + ei[NE + e]];
    g_coef[e]      = (dout > 0.0f) ? w / dout : 0.0f;  // coef_o
    g_coef[NE + e] = (din  > 0.0f) ? w / din  : 0.0f;  // coef_i
}

// -------- k4: exclusive scan of counts -> offsets (+cursors). 1 block. --------
__global__ void __launch_bounds__(1024) k_scan() {
    __shared__ int sums[1024];
    const int PER = 10;                       // 1024*10 >= 10000
    int t = threadIdx.x;
    int base = t * PER;
    int local[PER];
    int s = 0;
    #pragma unroll
    for (int i = 0; i < PER; i++) {
        int idx = base + i;
        int v = (idx < SCAN_N) ? g_cnt[idx] : 0;
        local[i] = s; s += v;
    }
    sums[t] = s;
    __syncthreads();
    // Hillis-Steele inclusive scan over 1024 partials
    for (int off = 1; off < 1024; off <<= 1) {
        int v = (t >= off) ? sums[t - off] : 0;
        __syncthreads();
        sums[t] += v;
        __syncthreads();
    }
    int carry = (t > 0) ? sums[t - 1] : 0;
    #pragma unroll
    for (int i = 0; i < PER; i++) {
        int idx = base + i;
        if (idx < SCAN_N) {
            int o = carry + local[i];
            g_off[idx] = o;
            g_cursor[idx] = o;
        }
    }
    if (t == 1023) g_off[SCAN_N] = carry + s;  // == 2*NE
}

// -------- k5: fill adjacency (nbr + coef packed at scan-assigned slots) --------
__global__ void k_fill(const int* __restrict__ ei) {
    int e = blockIdx.x * blockDim.x + threadIdx.x;
    if (e >= NE) return;
    int s = ei[e], d = ei[NE + e];
    int p = atomicAdd(&g_cursor[d], 1);        // in-CSR slot of node d
    g_adj_nbr[p]  = s;
    g_adj_coef[p] = g_coef[e];                 // coef_o
    int q = atomicAdd(&g_cursor[NN + s], 1);   // out-CSR slot of node s
    g_adj_nbr[q]  = d;
    g_adj_coef[q] = g_coef[NE + e];            // coef_i
}

// -------- k6: Mcat[:, :128] = X ; pad rows = 0 --------
__global__ void k_init(const float* __restrict__ x) {
    int idx = blockIdx.x * blockDim.x + threadIdx.x;  // float4 index
    const int XPART = MROWS * 32;                     // X copy region
    const int PADPART = (MPAD - MROWS) * 96;          // pad-row zero region
    if (idx < XPART) {
        int r = idx >> 5, c4 = idx & 31;
        reinterpret_cast<float4*>(g_Mcat)[(size_t)r * 96 + c4] =
            reinterpret_cast<const float4*>(x)[idx];
    } else if (idx < XPART + PADPART) {
        int j = idx - XPART;
        int r = MROWS + j / 96, c4 = j % 96;
        reinterpret_cast<float4*>(g_Mcat)[(size_t)r * 96 + c4] =
            make_float4(0.f, 0.f, 0.f, 0.f);
    }
}

// -------- k7: stacked weights Wcat[384,256] + bias --------
__global__ void k_weights(const float* __restrict__ Wz, const float* __restrict__ bz,
                          const float* __restrict__ Wh, const float* __restrict__ bh) {
    int id = blockIdx.x * blockDim.x + threadIdx.x;
    if (id >= KC * NC) return;
    int k = id / NC;
    int j = id % NC;
    const float* W = (j < 128) ? Wz : Wh;
    int jc = j & 127;
    float v;
    if (k < 128)      v = W[k * 128 + jc] + W[(2 * 256 + k) * 128 + jc]; // W[0,0]+W[1,0]
    else if (k < 256) v = W[(256 + (k - 128)) * 128 + jc];               // W[0,1]
    else              v = W[(3 * 256 + (k - 256)) * 128 + jc];           // W[1,1]
    g_Wcat[k * NC + j] = v;
    if (id < NC) g_bias[id] = (id < 128) ? bz[id] : bh[id - 128];
}

// -------- k8: CSR gather diffusion --------
// One warp per (direction, node, batch). 2*NN*NB = 40000 warps.
// half=0: Txo[v] = sum_in  coef_o * X[src]   (in-CSR region  [0, NN))
// half=1: Txi[v] = sum_out coef_i * X[dst]   (out-CSR region [NN, 2NN))
__global__ void k_gather(const float* __restrict__ x) {
    int gw = (blockIdx.x * blockDim.x + threadIdx.x) >> 5;
    int lane = threadIdx.x & 31;
    if (gw >= 2 * NN * NB) return;
    int half = gw / (NN * NB);
    int rem  = gw % (NN * NB);
    int v = rem / NB;          // adjacent warps share node -> adj reads hit L1
    int b = rem % NB;

    int slot = half * NN + v;
    int beg = g_off[slot];
    int end = g_off[slot + 1];

    const float4* X4 = reinterpret_cast<const float4*>(x);
    float4 acc = make_float4(0.f, 0.f, 0.f, 0.f);

    int p = beg;
    for (; p + 2 <= end; p += 2) {
        int   n0 = g_adj_nbr[p],      n1 = g_adj_nbr[p + 1];
        float c0 = g_adj_coef[p],     c1 = g_adj_coef[p + 1];
        float4 x0 = X4[(size_t)(b * NN + n0) * 32 + lane];
        float4 x1 = X4[(size_t)(b * NN + n1) * 32 + lane];
        acc.x = fmaf(c0, x0.x, acc.x); acc.y = fmaf(c0, x0.y, acc.y);
        acc.z = fmaf(c0, x0.z, acc.z); acc.w = fmaf(c0, x0.w, acc.w);
        acc.x = fmaf(c1, x1.x, acc.x); acc.y = fmaf(c1, x1.y, acc.y);
        acc.z = fmaf(c1, x1.z, acc.z); acc.w = fmaf(c1, x1.w, acc.w);
    }
    if (p < end) {
        int   n0 = g_adj_nbr[p];
        float c0 = g_adj_coef[p];
        float4 x0 = X4[(size_t)(b * NN + n0) * 32 + lane];
        acc.x = fmaf(c0, x0.x, acc.x); acc.y = fmaf(c0, x0.y, acc.y);
        acc.z = fmaf(c0, x0.z, acc.z); acc.w = fmaf(c0, x0.w, acc.w);
    }

    // Mcat row (b*NN+v): cols 128..255 = Txo (half 0), 256..383 = Txi (half 1)
    reinterpret_cast<float4*>(g_Mcat)[(size_t)(b * NN + v) * 96 + 32 + half * 32 + lane] = acc;
}

// -------- k9: SGEMM 64x256 tile + fused gate epilogue --------
// out[r, c] = (1 - sigmoid(D[r,c])) * tanh(D[r,c+128]),  D = Mcat @ Wcat + bias
#define GBM 64
#define GBK 16
#define ASTR 68   // padded, 16B-aligned row stride for As
__global__ void __launch_bounds__(256) k_gemm(float* __restrict__ out) {
    __shared__ float As[GBK][ASTR];   // transposed A tile [k][m]
    __shared__ float Bs[GBK][NC];
    int bm = blockIdx.x * GBM;
    int tid = threadIdx.x;
    int tx = tid & 31;    // col group: z cols tx*4.., h cols 128+tx*4..
    int ty = tid >> 5;    // row group: rows ty*8..

    float acc[8][8];
    #pragma unroll
    for (int i = 0; i < 8; i++)
        #pragma unroll
        for (int j = 0; j < 8; j++) acc[i][j] = 0.f;

    // A-load mapping (1 float4/thread): row=tid>>2, kq=(tid&3)*4
    int arow = tid >> 2;
    int akq  = (tid & 3) * 4;

    for (int k0 = 0; k0 < KC; k0 += GBK) {
        float4 va = *reinterpret_cast<const float4*>(
            &g_Mcat[(size_t)(bm + arow) * KC + k0 + akq]);
        float4 vb[4];
        #pragma unroll
        for (int i = 0; i < 4; i++) {
            int s = tid + i * 256;
            int krow = s >> 6;             // 0..15
            int cq   = (s & 63) * 4;       // 0..252
            vb[i] = *reinterpret_cast<const float4*>(&g_Wcat[(k0 + krow) * NC + cq]);
        }
        __syncthreads();   // previous iter's compute done before overwrite
        As[akq + 0][arow] = va.x;
        As[akq + 1][arow] = va.y;
        As[akq + 2][arow] = va.z;
        As[akq + 3][arow] = va.w;
        #pragma unroll
        for (int i = 0; i < 4; i++) {
            int s = tid + i * 256;
            *reinterpret_cast<float4*>(&Bs[s >> 6][(s & 63) * 4]) = vb[i];
        }
        __syncthreads();

        #pragma unroll
        for (int k = 0; k < GBK; k++) {
            float a[8], bb[8];
            *reinterpret_cast<float4*>(a)      = *reinterpret_cast<float4*>(&As[k][ty * 8]);
            *reinterpret_cast<float4*>(a + 4)  = *reinterpret_cast<float4*>(&As[k][ty * 8 + 4]);
            *reinterpret_cast<float4*>(bb)     = *reinterpret_cast<float4*>(&Bs[k][tx * 4]);
            *reinterpret_cast<float4*>(bb + 4) = *reinterpret_cast<float4*>(&Bs[k][128 + tx * 4]);
            #pragma unroll
            for (int i = 0; i < 8; i++)
                #pragma unroll
                for (int j = 0; j < 8; j++)
                    acc[i][j] = fmaf(a[i], bb[j], acc[i][j]);
        }
        __syncthreads();
    }

    // fused epilogue: bias + (1-sigmoid(z))*tanh(h), direct store to out
    float bzr[4], bhr[4];
    #pragma unroll
    for (int q = 0; q < 4; q++) {
        bzr[q] = g_bias[tx * 4 + q];
        bhr[q] = g_bias[128 + tx * 4 + q];
    }
    #pragma unroll
    for (int i = 0; i < 8; i++) {
        int r = bm + ty * 8 + i;
        if (r < MROWS) {
            float4 o;
            float z, h;
            z = acc[i][0] + bzr[0]; h = acc[i][4] + bhr[0];
            o.x = (1.0f / (1.0f + expf(z))) * tanhf(h);
            z = acc[i][1] + bzr[1]; h = acc[i][5] + bhr[1];
            o.y = (1.0f / (1.0f + expf(z))) * tanhf(h);
            z = acc[i][2] + bzr[2]; h = acc[i][6] + bhr[2];
            o.z = (1.0f / (1.0f + expf(z))) * tanhf(h);
            z = acc[i][3] + bzr[3]; h = acc[i][7] + bhr[3];
            o.w = (1.0f / (1.0f + expf(z))) * tanhf(h);
            *reinterpret_cast<float4*>(&out[(size_t)r * 128 + tx * 4]) = o;
        }
    }
}

extern "C" void kernel_launch(void* const* d_in, const int* in_sizes, int n_in,
                              void* d_out, int out_size) {
    const float* x  = (const float*)d_in[0];
    const int*   ei = (const int*)d_in[1];
    const float* ew = (const float*)d_in[2];
    const float* Wz = (const float*)d_in[3];
    const float* bz = (const float*)d_in[4];
    // d_in[5]=Wr, d_in[6]=br : dead (H0 == 0 => R multiplies zero)
    const float* Wh = (const float*)d_in[7];
    const float* bh = (const float*)d_in[8];
    float* out = (float*)d_out;

    k_zero  <<<(2 * NN + 255) / 256, 256>>>();
    k_degcnt<<<(NE + 255) / 256, 256>>>(ei, ew);
    k_coef  <<<(NE + 255) / 256, 256>>>(ei, ew);
    k_scan  <<<1, 1024>>>();
    k_fill  <<<(NE + 255) / 256, 256>>>(ei);
    k_init  <<<(MROWS * 32 + (MPAD - MROWS) * 96 + 255) / 256, 256>>>(x);
    k_weights<<<(KC * NC + 255) / 256, 256>>>(Wz, bz, Wh, bh);
    k_gather<<<(2 * NN * NB * 32 + 255) / 256, 256>>>(x);   // 40000 warps
    k_gemm  <<<MPAD / GBM, 256>>>(out);
}

// round 6
// speedup vs baseline: 1.3924x; 1.0250x over previous
#include <cuda_runtime.h>
#include <math.h>

// Problem constants (fixed shapes)
#define NB    4
#define NN    5000
#define SEQ   128
#define NE    80000
#define MROWS (NB*NN)   // 20000
#define MPAD  20096     // 314*64
#define KC    384       // [X | Txo | Txi] (X read straight from input)
#define NC    256       // [z | h]
#define SCAN_N (2*NN)   // 10000 combined CSR slots (in | out)

// -------- device scratch (static; zero-initialized at module load) --------
__device__ __align__(16) float g_T[(size_t)MPAD * 256];  // [Txo | Txi] rows; pad rows never written -> stay 0
__device__ __align__(16) float g_Wcat[KC * NC];
__device__ __align__(16) float g_bias[NC];
__device__ float g_deg[2 * NN];       // [deg_out | deg_in] (weighted)
__device__ int   g_cnt[SCAN_N];       // [in-count | out-count]
__device__ int   g_off[SCAN_N + 1];   // CSR offsets
__device__ int   g_cursor[SCAN_N];
__device__ int   g_adj_nbr[2 * NE];
__device__ float g_adj_coef[2 * NE];

// -------- k1: zero degrees + counts --------
__global__ void k_zero() {
    int i = blockIdx.x * blockDim.x + threadIdx.x;
    if (i < 2 * NN) { g_deg[i] = 0.0f; g_cnt[i] = 0; }
}

// -------- k2: weighted degrees + structural counts --------
__global__ void k_degcnt(const int* __restrict__ ei, const float* __restrict__ ew) {
    int e = blockIdx.x * blockDim.x + threadIdx.x;
    if (e >= NE) return;
    int s = ei[e], d = ei[NE + e];
    float w = ew[e];
    atomicAdd(&g_deg[s], w);          // deg_out[src]
    atomicAdd(&g_deg[NN + d], w);     // deg_in[dst]
    atomicAdd(&g_cnt[d], 1);          // in-count of dst  (Txo CSR)
    atomicAdd(&g_cnt[NN + s], 1);     // out-count of src (Txi CSR)
}

// -------- k3: exclusive scan via warp shuffles (2 barriers) --------
__global__ void __launch_bounds__(1024) k_scan() {
    __shared__ int warp_sums[32];
    const int PER = 10;                       // 1024*10 >= 10000
    int t = threadIdx.x;
    int lane = t & 31, wid = t >> 5;
    int base = t * PER;
    int local[PER];
    int s = 0;
    #pragma unroll
    for (int i = 0; i < PER; i++) {
        int idx = base + i;
        int v = (idx < SCAN_N) ? g_cnt[idx] : 0;
        local[i] = s; s += v;
    }
    // inclusive warp scan of per-thread sums
    int sc = s;
    #pragma unroll
    for (int o = 1; o < 32; o <<= 1) {
        int u = __shfl_up_sync(0xFFFFFFFFu, sc, o);
        if (lane >= o) sc += u;
    }
    if (lane == 31) warp_sums[wid] = sc;
    __syncthreads();
    if (wid == 0) {
        int ws = warp_sums[lane];
        #pragma unroll
        for (int o = 1; o < 32; o <<= 1) {
            int u = __shfl_up_sync(0xFFFFFFFFu, ws, o);
            if (lane >= o) ws += u;
        }
        warp_sums[lane] = ws;
    }
    __syncthreads();
    int carry = (sc - s) + (wid > 0 ? warp_sums[wid - 1] : 0);  // exclusive prefix
    #pragma unroll
    for (int i = 0; i < PER; i++) {
        int idx = base + i;
        if (idx < SCAN_N) {
            int o = carry + local[i];
            g_off[idx] = o;
            g_cursor[idx] = o;
        }
    }
    if (t == 1023) g_off[SCAN_N] = carry + s;   // == 2*NE
}

// -------- k4: fill adjacency; coefficients computed inline --------
__global__ void k_fill(const int* __restrict__ ei, const float* __restrict__ ew) {
    int e = blockIdx.x * blockDim.x + threadIdx.x;
    if (e >= NE) return;
    int s = ei[e], d = ei[NE + e];
    float w = ew[e];
    float dout = g_deg[s];
    float din  = g_deg[NN + d];
    int p = atomicAdd(&g_cursor[d], 1);          // in-CSR slot of d
    g_adj_nbr[p]  = s;
    g_adj_coef[p] = (dout > 0.0f) ? w / dout : 0.0f;  // coef_o
    int q = atomicAdd(&g_cursor[NN + s], 1);     // out-CSR slot of s
    g_adj_nbr[q]  = d;
    g_adj_coef[q] = (din > 0.0f) ? w / din : 0.0f;    // coef_i
}

// -------- k5: stacked weights Wcat[384,256] + bias --------
// W flattened (2,2,256,128): W[a][b][r][c] = ((a*2+b)*256 + r)*128 + c
__global__ void k_weights(const float* __restrict__ Wz, const float* __restrict__ bz,
                          const float* __restrict__ Wh, const float* __restrict__ bh) {
    int id = blockIdx.x * blockDim.x + threadIdx.x;
    if (id >= KC * NC) return;
    int k = id / NC;
    int j = id % NC;
    const float* W = (j < 128) ? Wz : Wh;
    int jc = j & 127;
    float v;
    if (k < 128)      v = W[k * 128 + jc] + W[(512 + k) * 128 + jc];  // W[0,0]+W[1,0]
    else if (k < 256) v = W[(256 + (k - 128)) * 128 + jc];            // W[0,1]
    else              v = W[(768 + (k - 256)) * 128 + jc];            // W[1,1]
    g_Wcat[k * NC + j] = v;
    if (id < NC) g_bias[id] = (id < 128) ? bz[id] : bh[id - 128];
}

// -------- k6: CSR gather diffusion --------
// Warp per (slot, batch): 2*NN*NB = 40000 warps. gw = slot*4 + b so
// adjacent warps share a slot -> adjacency loads are L1 broadcast hits.
// Unrolled x4 edges -> 4 independent X-row loads in flight per lane.
__global__ void k_gather(const float* __restrict__ x) {
    int gw = (blockIdx.x * blockDim.x + threadIdx.x) >> 5;
    int lane = threadIdx.x & 31;
    if (gw >= 2 * NN * NB) return;
    int slot = gw >> 2;          // 0..9999  (half*NN + v)
    int b    = gw & 3;
    int half = slot / NN;
    int v    = slot % NN;

    int beg = g_off[slot];
    int end = g_off[slot + 1];

    const float4* X4 = reinterpret_cast<const float4*>(x) + (size_t)b * NN * 32;
    float4 acc = make_float4(0.f, 0.f, 0.f, 0.f);

    int p = beg;
    for (; p + 4 <= end; p += 4) {
        int   n0 = g_adj_nbr[p],     n1 = g_adj_nbr[p + 1];
        int   n2 = g_adj_nbr[p + 2], n3 = g_adj_nbr[p + 3];
        float c0 = g_adj_coef[p],     c1 = g_adj_coef[p + 1];
        float c2 = g_adj_coef[p + 2], c3 = g_adj_coef[p + 3];
        float4 x0 = X4[(size_t)n0 * 32 + lane];
        float4 x1 = X4[(size_t)n1 * 32 + lane];
        float4 x2 = X4[(size_t)n2 * 32 + lane];
        float4 x3 = X4[(size_t)n3 * 32 + lane];
        acc.x = fmaf(c0, x0.x, acc.x); acc.y = fmaf(c0, x0.y, acc.y);
        acc.z = fmaf(c0, x0.z, acc.z); acc.w = fmaf(c0, x0.w, acc.w);
        acc.x = fmaf(c1, x1.x, acc.x); acc.y = fmaf(c1, x1.y, acc.y);
        acc.z = fmaf(c1, x1.z, acc.z); acc.w = fmaf(c1, x1.w, acc.w);
        acc.x = fmaf(c2, x2.x, acc.x); acc.y = fmaf(c2, x2.y, acc.y);
        acc.z = fmaf(c2, x2.z, acc.z); acc.w = fmaf(c2, x2.w, acc.w);
        acc.x = fmaf(c3, x3.x, acc.x); acc.y = fmaf(c3, x3.y, acc.y);
        acc.z = fmaf(c3, x3.z, acc.z); acc.w = fmaf(c3, x3.w, acc.w);
    }
    for (; p < end; p++) {
        int   n0 = g_adj_nbr[p];
        float c0 = g_adj_coef[p];
        float4 x0 = X4[(size_t)n0 * 32 + lane];
        acc.x = fmaf(c0, x0.x, acc.x); acc.y = fmaf(c0, x0.y, acc.y);
        acc.z = fmaf(c0, x0.z, acc.z); acc.w = fmaf(c0, x0.w, acc.w);
    }

    // g_T row (b*NN+v): cols [0,128)=Txo (half 0), [128,256)=Txi (half 1)
    reinterpret_cast<float4*>(g_T)[(size_t)(b * NN + v) * 64 + half * 32 + lane] = acc;
}

// -------- k7: SGEMM 64x256 + fused gate epilogue --------
// A[r,k]: k<128 -> x[r,k] ; k>=128 -> g_T[r,k-128] (pad rows of g_T are zero)
// out[r,c] = (1 - sigmoid(D[r,c])) * tanh(D[r,c+128])
#define GBM 64
#define GBK 16
#define ASTR 68
__global__ void __launch_bounds__(256) k_gemm(const float* __restrict__ x,
                                              float* __restrict__ out) {
    __shared__ float As[GBK][ASTR];
    __shared__ float Bs[GBK][NC];
    int bm = blockIdx.x * GBM;
    int tid = threadIdx.x;
    int tx = tid & 31;
    int ty = tid >> 5;

    float acc[8][8];
    #pragma unroll
    for (int i = 0; i < 8; i++)
        #pragma unroll
        for (int j = 0; j < 8; j++) acc[i][j] = 0.f;

    int arow = tid >> 2;            // 0..63
    int akq  = (tid & 3) * 4;       // 0,4,8,12
    int grow = bm + arow;
    int xrow = (grow < MROWS) ? grow : 0;   // clamp pad rows (stores guarded)

    for (int k0 = 0; k0 < KC; k0 += GBK) {
        float4 va;
        if (k0 < 128)
            va = *reinterpret_cast<const float4*>(&x[(size_t)xrow * 128 + k0 + akq]);
        else
            va = *reinterpret_cast<const float4*>(&g_T[(size_t)grow * 256 + (k0 - 128) + akq]);
        float4 vb[4];
        #pragma unroll
        for (int i = 0; i < 4; i++) {
            int s = tid + i * 256;
            vb[i] = *reinterpret_cast<const float4*>(&g_Wcat[(k0 + (s >> 6)) * NC + (s & 63) * 4]);
        }
        __syncthreads();
        As[akq + 0][arow] = va.x;
        As[akq + 1][arow] = va.y;
        As[akq + 2][arow] = va.z;
        As[akq + 3][arow] = va.w;
        #pragma unroll
        for (int i = 0; i < 4; i++) {
            int s = tid + i * 256;
            *reinterpret_cast<float4*>(&Bs[s >> 6][(s & 63) * 4]) = vb[i];
        }
        __syncthreads();

        #pragma unroll
        for (int k = 0; k < GBK; k++) {
            float a[8], bb[8];
            *reinterpret_cast<float4*>(a)      = *reinterpret_cast<float4*>(&As[k][ty * 8]);
            *reinterpret_cast<float4*>(a + 4)  = *reinterpret_cast<float4*>(&As[k][ty * 8 + 4]);
            *reinterpret_cast<float4*>(bb)     = *reinterpret_cast<float4*>(&Bs[k][tx * 4]);
            *reinterpret_cast<float4*>(bb + 4) = *reinterpret_cast<float4*>(&Bs[k][128 + tx * 4]);
            #pragma unroll
            for (int i = 0; i < 8; i++)
                #pragma unroll
                for (int j = 0; j < 8; j++)
                    acc[i][j] = fmaf(a[i], bb[j], acc[i][j]);
        }
        __syncthreads();
    }

    float bzr[4], bhr[4];
    #pragma unroll
    for (int q = 0; q < 4; q++) {
        bzr[q] = g_bias[tx * 4 + q];
        bhr[q] = g_bias[128 + tx * 4 + q];
    }
    #pragma unroll
    for (int i = 0; i < 8; i++) {
        int r = bm + ty * 8 + i;
        if (r < MROWS) {
            float4 o;
            float z, h;
            z = acc[i][0] + bzr[0]; h = acc[i][4] + bhr[0];
            o.x = (1.0f / (1.0f + expf(z))) * tanhf(h);
            z = acc[i][1] + bzr[1]; h = acc[i][5] + bhr[1];
            o.y = (1.0f / (1.0f + expf(z))) * tanhf(h);
            z = acc[i][2] + bzr[2]; h = acc[i][6] + bhr[2];
            o.z = (1.0f / (1.0f + expf(z))) * tanhf(h);
            z = acc[i][3] + bzr[3]; h = acc[i][7] + bhr[3];
            o.w = (1.0f / (1.0f + expf(z))) * tanhf(h);
            *reinterpret_cast<float4*>(&out[(size_t)r * 128 + tx * 4]) = o;
        }
    }
}

extern "C" void kernel_launch(void* const* d_in, const int* in_sizes, int n_in,
                              void* d_out, int out_size) {
    const float* x  = (const float*)d_in[0];
    const int*   ei = (const int*)d_in[1];
    const float* ew = (const float*)d_in[2];
    const float* Wz = (const float*)d_in[3];
    const float* bz = (const float*)d_in[4];
    // d_in[5]=Wr, d_in[6]=br : dead (H0 == 0 => R multiplies zero)
    const float* Wh = (const float*)d_in[7];
    const float* bh = (const float*)d_in[8];
    float* out = (float*)d_out;

    k_zero   <<<(2 * NN + 255) / 256, 256>>>();                 // #1
    k_degcnt <<<(NE + 255) / 256, 256>>>(ei, ew);               // #2
    k_scan   <<<1, 1024>>>();                                   // #3
    k_fill   <<<(NE + 255) / 256, 256>>>(ei, ew);               // #4
    k_weights<<<(KC * NC + 255) / 256, 256>>>(Wz, bz, Wh, bh);  // #5
    k_gather <<<(2 * NN * NB * 32 + 255) / 256, 256>>>(x);      // #6  <- ncu -s 5 lands here
    k_gemm   <<<MPAD / GBM, 256>>>(x, out);                     // #7
}

// round 7
// speedup vs baseline: 1.4897x; 1.0699x over previous
#include <cuda_runtime.h>
#include <math.h>

// Problem constants (fixed shapes)
#define NB    4
#define NN    5000
#define SEQ   128
#define NE    80000
#define MROWS (NB*NN)   // 20000
#define MPAD  20096     // 314*64
#define KC    384       // [X | Txo | Txi]
#define NC    256       // [z | h]
#define SCAN_N (2*NN)

typedef unsigned long long u64;

// -------- device scratch (static; zero-initialized at module load) --------
__device__ __align__(16) float g_T[(size_t)MPAD * 256];  // [Txo | Txi]; pad rows never written -> stay 0
__device__ __align__(16) float g_Wcat[KC * NC];
__device__ __align__(16) float g_bias[NC];
__device__ float g_deg[2 * NN];
__device__ int   g_cnt[SCAN_N];
__device__ int   g_off[SCAN_N + 1];
__device__ int   g_cursor[SCAN_N];
__device__ int   g_adj_nbr[2 * NE];
__device__ float g_adj_coef[2 * NE];

// -------- k1: zero degrees + counts --------
__global__ void k_zero() {
    int i = blockIdx.x * blockDim.x + threadIdx.x;
    if (i < 2 * NN) { g_deg[i] = 0.0f; g_cnt[i] = 0; }
}

// -------- k2: weighted degrees + structural counts --------
__global__ void k_degcnt(const int* __restrict__ ei, const float* __restrict__ ew) {
    int e = blockIdx.x * blockDim.x + threadIdx.x;
    if (e >= NE) return;
    int s = ei[e], d = ei[NE + e];
    float w = ew[e];
    atomicAdd(&g_deg[s], w);
    atomicAdd(&g_deg[NN + d], w);
    atomicAdd(&g_cnt[d], 1);
    atomicAdd(&g_cnt[NN + s], 1);
}

// -------- k3: exclusive scan via warp shuffles --------
__global__ void __launch_bounds__(1024) k_scan() {
    __shared__ int warp_sums[32];
    const int PER = 10;
    int t = threadIdx.x;
    int lane = t & 31, wid = t >> 5;
    int base = t * PER;
    int local[PER];
    int s = 0;
    #pragma unroll
    for (int i = 0; i < PER; i++) {
        int idx = base + i;
        int v = (idx < SCAN_N) ? g_cnt[idx] : 0;
        local[i] = s; s += v;
    }
    int sc = s;
    #pragma unroll
    for (int o = 1; o < 32; o <<= 1) {
        int u = __shfl_up_sync(0xFFFFFFFFu, sc, o);
        if (lane >= o) sc += u;
    }
    if (lane == 31) warp_sums[wid] = sc;
    __syncthreads();
    if (wid == 0) {
        int ws = warp_sums[lane];
        #pragma unroll
        for (int o = 1; o < 32; o <<= 1) {
            int u = __shfl_up_sync(0xFFFFFFFFu, ws, o);
            if (lane >= o) ws += u;
        }
        warp_sums[lane] = ws;
    }
    __syncthreads();
    int carry = (sc - s) + (wid > 0 ? warp_sums[wid - 1] : 0);
    #pragma unroll
    for (int i = 0; i < PER; i++) {
        int idx = base + i;
        if (idx < SCAN_N) {
            int o = carry + local[i];
            g_off[idx] = o;
            g_cursor[idx] = o;
        }
    }
    if (t == 1023) g_off[SCAN_N] = carry + s;
}

// -------- k4: fill adjacency; coefficients inline --------
__global__ void k_fill(const int* __restrict__ ei, const float* __restrict__ ew) {
    int e = blockIdx.x * blockDim.x + threadIdx.x;
    if (e >= NE) return;
    int s = ei[e], d = ei[NE + e];
    float w = ew[e];
    float dout = g_deg[s];
    float din  = g_deg[NN + d];
    int p = atomicAdd(&g_cursor[d], 1);
    g_adj_nbr[p]  = s;
    g_adj_coef[p] = (dout > 0.0f) ? w / dout : 0.0f;
    int q = atomicAdd(&g_cursor[NN + s], 1);
    g_adj_nbr[q]  = d;
    g_adj_coef[q] = (din > 0.0f) ? w / din : 0.0f;
}

// -------- k5: stacked weights Wcat[384,256] + bias --------
__global__ void k_weights(const float* __restrict__ Wz, const float* __restrict__ bz,
                          const float* __restrict__ Wh, const float* __restrict__ bh) {
    int id = blockIdx.x * blockDim.x + threadIdx.x;
    if (id >= KC * NC) return;
    int k = id / NC;
    int j = id % NC;
    const float* W = (j < 128) ? Wz : Wh;
    int jc = j & 127;
    float v;
    if (k < 128)      v = W[k * 128 + jc] + W[(512 + k) * 128 + jc];
    else if (k < 256) v = W[(256 + (k - 128)) * 128 + jc];
    else              v = W[(768 + (k - 256)) * 128 + jc];
    g_Wcat[k * NC + j] = v;
    if (id < NC) g_bias[id] = (id < 128) ? bz[id] : bh[id - 128];
}

// -------- k6: CSR gather diffusion --------
__global__ void k_gather(const float* __restrict__ x) {
    int gw = (blockIdx.x * blockDim.x + threadIdx.x) >> 5;
    int lane = threadIdx.x & 31;
    if (gw >= 2 * NN * NB) return;
    int slot = gw >> 2;
    int b    = gw & 3;
    int half = slot / NN;
    int v    = slot % NN;

    int beg = g_off[slot];
    int end = g_off[slot + 1];

    const float4* X4 = reinterpret_cast<const float4*>(x) + (size_t)b * NN * 32;
    float4 acc = make_float4(0.f, 0.f, 0.f, 0.f);

    int p = beg;
    for (; p + 4 <= end; p += 4) {
        int   n0 = g_adj_nbr[p],     n1 = g_adj_nbr[p + 1];
        int   n2 = g_adj_nbr[p + 2], n3 = g_adj_nbr[p + 3];
        float c0 = g_adj_coef[p],     c1 = g_adj_coef[p + 1];
        float c2 = g_adj_coef[p + 2], c3 = g_adj_coef[p + 3];
        float4 x0 = X4[(size_t)n0 * 32 + lane];
        float4 x1 = X4[(size_t)n1 * 32 + lane];
        float4 x2 = X4[(size_t)n2 * 32 + lane];
        float4 x3 = X4[(size_t)n3 * 32 + lane];
        acc.x = fmaf(c0, x0.x, acc.x); acc.y = fmaf(c0, x0.y, acc.y);
        acc.z = fmaf(c0, x0.z, acc.z); acc.w = fmaf(c0, x0.w, acc.w);
        acc.x = fmaf(c1, x1.x, acc.x); acc.y = fmaf(c1, x1.y, acc.y);
        acc.z = fmaf(c1, x1.z, acc.z); acc.w = fmaf(c1, x1.w, acc.w);
        acc.x = fmaf(c2, x2.x, acc.x); acc.y = fmaf(c2, x2.y, acc.y);
        acc.z = fmaf(c2, x2.z, acc.z); acc.w = fmaf(c2, x2.w, acc.w);
        acc.x = fmaf(c3, x3.x, acc.x); acc.y = fmaf(c3, x3.y, acc.y);
        acc.z = fmaf(c3, x3.z, acc.z); acc.w = fmaf(c3, x3.w, acc.w);
    }
    for (; p < end; p++) {
        int   n0 = g_adj_nbr[p];
        float c0 = g_adj_coef[p];
        float4 x0 = X4[(size_t)n0 * 32 + lane];
        acc.x = fmaf(c0, x0.x, acc.x); acc.y = fmaf(c0, x0.y, acc.y);
        acc.z = fmaf(c0, x0.z, acc.z); acc.w = fmaf(c0, x0.w, acc.w);
    }

    reinterpret_cast<float4*>(g_T)[(size_t)(b * NN + v) * 64 + half * 32 + lane] = acc;
}

// -------- k7: SGEMM 64x256 (packed f32x2 FMA) + fused gate epilogue --------
#define GBM 64
#define GBK 16
#define ASTR 68

__device__ __forceinline__ void fma2(u64& acc, u64 a, u64 b) {
    asm("fma.rn.f32x2 %0, %1, %2, %0;" : "+l"(acc) : "l"(a), "l"(b));
}

__global__ void __launch_bounds__(256) k_gemm(const float* __restrict__ x,
                                              float* __restrict__ out) {
    __shared__ float As[GBK][ASTR];
    __shared__ float Bs[GBK][NC];
    int bm = blockIdx.x * GBM;
    int tid = threadIdx.x;
    int tx = tid & 31;    // col group: z cols tx*4.., h cols 128+tx*4..
    int ty = tid >> 5;    // row group: rows ty*8..

    // acc64[i][0..1] = z-cols (tx*4+0,1),(tx*4+2,3) ; [2..3] = h-cols
    u64 acc64[8][4];
    #pragma unroll
    for (int i = 0; i < 8; i++)
        #pragma unroll
        for (int j = 0; j < 4; j++) acc64[i][j] = 0ull;

    int arow = tid >> 2;
    int akq  = (tid & 3) * 4;
    int grow = bm + arow;
    int xrow = (grow < MROWS) ? grow : 0;   // clamp pad rows (stores guarded)

    for (int k0 = 0; k0 < KC; k0 += GBK) {
        float4 va;
        if (k0 < 128)
            va = *reinterpret_cast<const float4*>(&x[(size_t)xrow * 128 + k0 + akq]);
        else
            va = *reinterpret_cast<const float4*>(&g_T[(size_t)grow * 256 + (k0 - 128) + akq]);
        float4 vb[4];
        #pragma unroll
        for (int i = 0; i < 4; i++) {
            int s = tid + i * 256;
            vb[i] = *reinterpret_cast<const float4*>(&g_Wcat[(k0 + (s >> 6)) * NC + (s & 63) * 4]);
        }
        __syncthreads();
        As[akq + 0][arow] = va.x;
        As[akq + 1][arow] = va.y;
        As[akq + 2][arow] = va.z;
        As[akq + 3][arow] = va.w;
        #pragma unroll
        for (int i = 0; i < 4; i++) {
            int s = tid + i * 256;
            *reinterpret_cast<float4*>(&Bs[s >> 6][(s & 63) * 4]) = vb[i];
        }
        __syncthreads();

        #pragma unroll
        for (int k = 0; k < GBK; k++) {
            float a[8];
            *reinterpret_cast<float4*>(a)     = *reinterpret_cast<float4*>(&As[k][ty * 8]);
            *reinterpret_cast<float4*>(a + 4) = *reinterpret_cast<float4*>(&As[k][ty * 8 + 4]);
            // 16B smem loads give two packed f32x2 values for free
            ulonglong2 bz2 = *reinterpret_cast<ulonglong2*>(&Bs[k][tx * 4]);
            ulonglong2 bh2 = *reinterpret_cast<ulonglong2*>(&Bs[k][128 + tx * 4]);
            #pragma unroll
            for (int i = 0; i < 8; i++) {
                u64 ad;
                asm("mov.b64 %0, {%1, %1};" : "=l"(ad) : "r"(__float_as_uint(a[i])));
                fma2(acc64[i][0], ad, bz2.x);
                fma2(acc64[i][1], ad, bz2.y);
                fma2(acc64[i][2], ad, bh2.x);
                fma2(acc64[i][3], ad, bh2.y);
            }
        }
        __syncthreads();
    }

    // fused epilogue: bias + (1-sigmoid(z))*tanh(h), direct store
    float bzr[4], bhr[4];
    #pragma unroll
    for (int q = 0; q < 4; q++) {
        bzr[q] = g_bias[tx * 4 + q];
        bhr[q] = g_bias[128 + tx * 4 + q];
    }
    #pragma unroll
    for (int i = 0; i < 8; i++) {
        int r = bm + ty * 8 + i;
        if (r < MROWS) {
            unsigned z0u, z1u, z2u, z3u, h0u, h1u, h2u, h3u;
            asm("mov.b64 {%0, %1}, %2;" : "=r"(z0u), "=r"(z1u) : "l"(acc64[i][0]));
            asm("mov.b64 {%0, %1}, %2;" : "=r"(z2u), "=r"(z3u) : "l"(acc64[i][1]));
            asm("mov.b64 {%0, %1}, %2;" : "=r"(h0u), "=r"(h1u) : "l"(acc64[i][2]));
            asm("mov.b64 {%0, %1}, %2;" : "=r"(h2u), "=r"(h3u) : "l"(acc64[i][3]));
            float4 o;
            float z, h;
            z = __uint_as_float(z0u) + bzr[0]; h = __uint_as_float(h0u) + bhr[0];
            o.x = (1.0f / (1.0f + expf(z))) * tanhf(h);
            z = __uint_as_float(z1u) + bzr[1]; h = __uint_as_float(h1u) + bhr[1];
            o.y = (1.0f / (1.0f + expf(z))) * tanhf(h);
            z = __uint_as_float(z2u) + bzr[2]; h = __uint_as_float(h2u) + bhr[2];
            o.z = (1.0f / (1.0f + expf(z))) * tanhf(h);
            z = __uint_as_float(z3u) + bzr[3]; h = __uint_as_float(h3u) + bhr[3];
            o.w = (1.0f / (1.0f + expf(z))) * tanhf(h);
            *reinterpret_cast<float4*>(&out[(size_t)r * 128 + tx * 4]) = o;
        }
    }
}

extern "C" void kernel_launch(void* const* d_in, const int* in_sizes, int n_in,
                              void* d_out, int out_size) {
    const float* x  = (const float*)d_in[0];
    const int*   ei = (const int*)d_in[1];
    const float* ew = (const float*)d_in[2];
    const float* Wz = (const float*)d_in[3];
    const float* bz = (const float*)d_in[4];
    // d_in[5]=Wr, d_in[6]=br : dead (H0 == 0 => R multiplies zero)
    const float* Wh = (const float*)d_in[7];
    const float* bh = (const float*)d_in[8];
    float* out = (float*)d_out;

    k_zero   <<<(2 * NN + 255) / 256, 256>>>();
    k_degcnt <<<(NE + 255) / 256, 256>>>(ei, ew);
    k_scan   <<<1, 1024>>>();
    k_fill   <<<(NE + 255) / 256, 256>>>(ei, ew);
    k_weights<<<(KC * NC + 255) / 256, 256>>>(Wz, bz, Wh, bh);
    k_gather <<<(2 * NN * NB * 32 + 255) / 256, 256>>>(x);
    k_gemm   <<<MPAD / GBM, 256>>>(x, out);
}

// round 8
// speedup vs baseline: 2.0422x; 1.3708x over previous
#include <cuda_runtime.h>
#include <cuda_bf16.h>
#include <math.h>

// Problem constants (fixed shapes)
#define NB    4
#define NN    5000
#define NE    80000
#define MROWS 20000
#define MPAD  20096     // 314*64
#define KC    384       // [X | Txo | Txi]
#define NC    256       // [z | h]
#define SCAN_N (2*NN)

typedef unsigned int u32;

// -------- device scratch (static; zero-initialized at module load) --------
__device__ __align__(16) float g_T[(size_t)MPAD * 256];  // [Txo | Txi]; pad rows stay 0
__device__ __align__(16) __nv_bfloat16 g_Wt_hi[NC * KC]; // Wcat^T [n][k], bf16 hi
__device__ __align__(16) __nv_bfloat16 g_Wt_lo[NC * KC]; // residual lo
__device__ __align__(16) float g_bias[NC];
__device__ float g_deg[2 * NN];
__device__ int   g_cnt[SCAN_N];
__device__ int   g_off[SCAN_N + 1];
__device__ int   g_cursor[SCAN_N];
__device__ int   g_adj_nbr[2 * NE];
__device__ float g_adj_coef[2 * NE];

// -------- k1: zero degrees + counts --------
__global__ void k_zero() {
    int i = blockIdx.x * blockDim.x + threadIdx.x;
    if (i < 2 * NN) { g_deg[i] = 0.0f; g_cnt[i] = 0; }
}

// -------- k2: weighted degrees + structural counts --------
__global__ void k_degcnt(const int* __restrict__ ei, const float* __restrict__ ew) {
    int e = blockIdx.x * blockDim.x + threadIdx.x;
    if (e >= NE) return;
    int s = ei[e], d = ei[NE + e];
    float w = ew[e];
    atomicAdd(&g_deg[s], w);
    atomicAdd(&g_deg[NN + d], w);
    atomicAdd(&g_cnt[d], 1);
    atomicAdd(&g_cnt[NN + s], 1);
}

// -------- k3: exclusive scan via warp shuffles --------
__global__ void __launch_bounds__(1024) k_scan() {
    __shared__ int warp_sums[32];
    const int PER = 10;
    int t = threadIdx.x;
    int lane = t & 31, wid = t >> 5;
    int base = t * PER;
    int local[PER];
    int s = 0;
    #pragma unroll
    for (int i = 0; i < PER; i++) {
        int idx = base + i;
        int v = (idx < SCAN_N) ? g_cnt[idx] : 0;
        local[i] = s; s += v;
    }
    int sc = s;
    #pragma unroll
    for (int o = 1; o < 32; o <<= 1) {
        int u = __shfl_up_sync(0xFFFFFFFFu, sc, o);
        if (lane >= o) sc += u;
    }
    if (lane == 31) warp_sums[wid] = sc;
    __syncthreads();
    if (wid == 0) {
        int ws = warp_sums[lane];
        #pragma unroll
        for (int o = 1; o < 32; o <<= 1) {
            int u = __shfl_up_sync(0xFFFFFFFFu, ws, o);
            if (lane >= o) ws += u;
        }
        warp_sums[lane] = ws;
    }
    __syncthreads();
    int carry = (sc - s) + (wid > 0 ? warp_sums[wid - 1] : 0);
    #pragma unroll
    for (int i = 0; i < PER; i++) {
        int idx = base + i;
        if (idx < SCAN_N) {
            int o = carry + local[i];
            g_off[idx] = o;
            g_cursor[idx] = o;
        }
    }
    if (t == 1023) g_off[SCAN_N] = carry + s;
}

// -------- k4: fill adjacency; coefficients inline --------
__global__ void k_fill(const int* __restrict__ ei, const float* __restrict__ ew) {
    int e = blockIdx.x * blockDim.x + threadIdx.x;
    if (e >= NE) return;
    int s = ei[e], d = ei[NE + e];
    float w = ew[e];
    float dout = g_deg[s];
    float din  = g_deg[NN + d];
    int p = atomicAdd(&g_cursor[d], 1);
    g_adj_nbr[p]  = s;
    g_adj_coef[p] = (dout > 0.0f) ? w / dout : 0.0f;
    int q = atomicAdd(&g_cursor[NN + s], 1);
    g_adj_nbr[q]  = d;
    g_adj_coef[q] = (din > 0.0f) ? w / din : 0.0f;
}

// -------- k5: stacked weights -> transposed bf16 hi/lo + bias --------
// Logical Wcat[k][j] (384x256); stored transposed g_Wt_*[j][k] as bf16 split.
__global__ void k_weights(const float* __restrict__ Wz, const float* __restrict__ bz,
                          const float* __restrict__ Wh, const float* __restrict__ bh) {
    int id = blockIdx.x * blockDim.x + threadIdx.x;
    if (id >= KC * NC) return;
    int k = id / NC;
    int j = id % NC;
    const float* W = (j < 128) ? Wz : Wh;
    int jc = j & 127;
    float v;
    if (k < 128)      v = W[k * 128 + jc] + W[(512 + k) * 128 + jc];  // W[0,0]+W[1,0]
    else if (k < 256) v = W[(256 + (k - 128)) * 128 + jc];            // W[0,1]
    else              v = W[(768 + (k - 256)) * 128 + jc];            // W[1,1]
    __nv_bfloat16 hi = __float2bfloat16_rn(v);
    __nv_bfloat16 lo = __float2bfloat16_rn(v - __bfloat162float(hi));
    g_Wt_hi[j * KC + k] = hi;
    g_Wt_lo[j * KC + k] = lo;
    if (id < NC) g_bias[id] = (id < 128) ? bz[id] : bh[id - 128];
}

// -------- k6: CSR gather diffusion (unchanged) --------
__global__ void k_gather(const float* __restrict__ x) {
    int gw = (blockIdx.x * blockDim.x + threadIdx.x) >> 5;
    int lane = threadIdx.x & 31;
    if (gw >= 2 * NN * NB) return;
    int slot = gw >> 2;
    int b    = gw & 3;
    int half = slot / NN;
    int v    = slot % NN;

    int beg = g_off[slot];
    int end = g_off[slot + 1];

    const float4* X4 = reinterpret_cast<const float4*>(x) + (size_t)b * NN * 32;
    float4 acc = make_float4(0.f, 0.f, 0.f, 0.f);

    int p = beg;
    for (; p + 4 <= end; p += 4) {
        int   n0 = g_adj_nbr[p],     n1 = g_adj_nbr[p + 1];
        int   n2 = g_adj_nbr[p + 2], n3 = g_adj_nbr[p + 3];
        float c0 = g_adj_coef[p],     c1 = g_adj_coef[p + 1];
        float c2 = g_adj_coef[p + 2], c3 = g_adj_coef[p + 3];
        float4 x0 = X4[(size_t)n0 * 32 + lane];
        float4 x1 = X4[(size_t)n1 * 32 + lane];
        float4 x2 = X4[(size_t)n2 * 32 + lane];
        float4 x3 = X4[(size_t)n3 * 32 + lane];
        acc.x = fmaf(c0, x0.x, acc.x); acc.y = fmaf(c0, x0.y, acc.y);
        acc.z = fmaf(c0, x0.z, acc.z); acc.w = fmaf(c0, x0.w, acc.w);
        acc.x = fmaf(c1, x1.x, acc.x); acc.y = fmaf(c1, x1.y, acc.y);
        acc.z = fmaf(c1, x1.z, acc.z); acc.w = fmaf(c1, x1.w, acc.w);
        acc.x = fmaf(c2, x2.x, acc.x); acc.y = fmaf(c2, x2.y, acc.y);
        acc.z = fmaf(c2, x2.z, acc.z); acc.w = fmaf(c2, x2.w, acc.w);
        acc.x = fmaf(c3, x3.x, acc.x); acc.y = fmaf(c3, x3.y, acc.y);
        acc.z = fmaf(c3, x3.z, acc.z); acc.w = fmaf(c3, x3.w, acc.w);
    }
    for (; p < end; p++) {
        int   n0 = g_adj_nbr[p];
        float c0 = g_adj_coef[p];
        float4 x0 = X4[(size_t)n0 * 32 + lane];
        acc.x = fmaf(c0, x0.x, acc.x); acc.y = fmaf(c0, x0.y, acc.y);
        acc.z = fmaf(c0, x0.z, acc.z); acc.w = fmaf(c0, x0.w, acc.w);
    }

    reinterpret_cast<float4*>(g_T)[(size_t)(b * NN + v) * 64 + half * 32 + lane] = acc;
}

// -------- k7: tensor-core GEMM (bf16x3 split) + fused gate epilogue --------
// D[MPAD,256] = A[MPAD,384] @ Wcat[384,256];  A: k<128 from x, k>=128 from g_T.
// out[r,c] = (1 - sigmoid(D[r,c] + bias[c])) * tanh(D[r,c+128] + bias[c+128])
#define GBM 64
#define GBK 32
#define ASTR 40   // A smem row stride (bf16): 20 banks -> conflict-free frags
#define BSTR 36   // B smem row stride (bf16): 18 banks -> near-conflict-free

#define MMA_BF16(c, a0, a1, a2, a3, b0, b1)                                \
    asm("mma.sync.aligned.m16n8k16.row.col.f32.bf16.bf16.f32 "             \
        "{%0,%1,%2,%3}, {%4,%5,%6,%7}, {%8,%9}, {%0,%1,%2,%3};"            \
        : "+f"((c)[0]), "+f"((c)[1]), "+f"((c)[2]), "+f"((c)[3])           \
        : "r"(a0), "r"(a1), "r"(a2), "r"(a3), "r"(b0), "r"(b1))

__device__ __forceinline__ void cvt_store8(__nv_bfloat16* hi, __nv_bfloat16* lo,
                                           int off, float4 v) {
    __nv_bfloat16 h0 = __float2bfloat16_rn(v.x);
    __nv_bfloat16 h1 = __float2bfloat16_rn(v.y);
    __nv_bfloat16 h2 = __float2bfloat16_rn(v.z);
    __nv_bfloat16 h3 = __float2bfloat16_rn(v.w);
    __nv_bfloat16 l0 = __float2bfloat16_rn(v.x - __bfloat162float(h0));
    __nv_bfloat16 l1 = __float2bfloat16_rn(v.y - __bfloat162float(h1));
    __nv_bfloat16 l2 = __float2bfloat16_rn(v.z - __bfloat162float(h2));
    __nv_bfloat16 l3 = __float2bfloat16_rn(v.w - __bfloat162float(h3));
    __nv_bfloat162 H0 = __nv_bfloat162(h0, h1), H1 = __nv_bfloat162(h2, h3);
    __nv_bfloat162 L0 = __nv_bfloat162(l0, l1), L1 = __nv_bfloat162(l2, l3);
    uint2 uh = make_uint2(*reinterpret_cast<u32*>(&H0), *reinterpret_cast<u32*>(&H1));
    uint2 ul = make_uint2(*reinterpret_cast<u32*>(&L0), *reinterpret_cast<u32*>(&L1));
    *reinterpret_cast<uint2*>(&hi[off]) = uh;
    *reinterpret_cast<uint2*>(&lo[off]) = ul;
}

__global__ void __launch_bounds__(256) k_gemm(const float* __restrict__ x,
                                              float* __restrict__ out) {
    __shared__ __nv_bfloat16 As_hi[GBM * ASTR];     // 5120 B
    __shared__ __nv_bfloat16 As_lo[GBM * ASTR];
    __shared__ __nv_bfloat16 Bs_hi[NC * BSTR];      // 18432 B
    __shared__ __nv_bfloat16 Bs_lo[NC * BSTR];

    int tid = threadIdx.x;
    int w = tid >> 5, lane = tid & 31;
    int g = lane >> 2, t = lane & 3;
    int bm = blockIdx.x * GBM;

    // acc[mi][zh][nj][4]: warp w covers z-cols [w*16, w*16+16) and h-cols +128
    float acc[4][2][2][4];
    #pragma unroll
    for (int mi = 0; mi < 4; mi++)
        #pragma unroll
        for (int zh = 0; zh < 2; zh++)
            #pragma unroll
            for (int nj = 0; nj < 2; nj++)
                #pragma unroll
                for (int q = 0; q < 4; q++) acc[mi][zh][nj][q] = 0.f;

    // A global-load mapping: 2 float4/thread, row = idx>>3, kq = (idx&7)*4
    int arow0 = tid >> 3,         akq0 = (tid & 7) * 4;
    int arow1 = (tid + 256) >> 3, akq1 = akq0;   // (tid+256)&7 == tid&7
    int gr0 = bm + arow0, gr1 = bm + arow1;
    int xr0 = (gr0 < MROWS) ? gr0 : 0;
    int xr1 = (gr1 < MROWS) ? gr1 : 0;
    // B mapping: 4 float4/thread per hi/lo: n = (tid+j*256)>>2, kq8 = (tid&3)*8
    int bkq = (tid & 3) * 8;
    int bn0 = tid >> 2, bn1 = (tid + 256) >> 2, bn2 = (tid + 512) >> 2, bn3 = (tid + 768) >> 2;

    for (int k0 = 0; k0 < KC; k0 += GBK) {
        // ---- global loads into regs ----
        float4 va0, va1;
        if (k0 < 128) {
            va0 = *reinterpret_cast<const float4*>(&x[(size_t)xr0 * 128 + k0 + akq0]);
            va1 = *reinterpret_cast<const float4*>(&x[(size_t)xr1 * 128 + k0 + akq1]);
        } else {
            va0 = *reinterpret_cast<const float4*>(&g_T[(size_t)gr0 * 256 + (k0 - 128) + akq0]);
            va1 = *reinterpret_cast<const float4*>(&g_T[(size_t)gr1 * 256 + (k0 - 128) + akq1]);
        }
        float4 vbh0 = *reinterpret_cast<const float4*>(&g_Wt_hi[bn0 * KC + k0 + bkq]);
        float4 vbh1 = *reinterpret_cast<const float4*>(&g_Wt_hi[bn1 * KC + k0 + bkq]);
        float4 vbh2 = *reinterpret_cast<const float4*>(&g_Wt_hi[bn2 * KC + k0 + bkq]);
        float4 vbh3 = *reinterpret_cast<const float4*>(&g_Wt_hi[bn3 * KC + k0 + bkq]);
        float4 vbl0 = *reinterpret_cast<const float4*>(&g_Wt_lo[bn0 * KC + k0 + bkq]);
        float4 vbl1 = *reinterpret_cast<const float4*>(&g_Wt_lo[bn1 * KC + k0 + bkq]);
        float4 vbl2 = *reinterpret_cast<const float4*>(&g_Wt_lo[bn2 * KC + k0 + bkq]);
        float4 vbl3 = *reinterpret_cast<const float4*>(&g_Wt_lo[bn3 * KC + k0 + bkq]);

        __syncthreads();   // previous iter's compute done before smem overwrite

        // ---- A: convert f32 -> bf16 hi/lo, store ----
        cvt_store8(As_hi, As_lo, arow0 * ASTR + akq0, va0);
        cvt_store8(As_hi, As_lo, arow1 * ASTR + akq1, va1);
        // ---- B: store 16B as 2x8B (BSTR row not 16B aligned) ----
        {
            uint4 u;
            u = *reinterpret_cast<uint4*>(&vbh0);
            *reinterpret_cast<uint2*>(&Bs_hi[bn0 * BSTR + bkq])     = make_uint2(u.x, u.y);
            *reinterpret_cast<uint2*>(&Bs_hi[bn0 * BSTR + bkq + 4]) = make_uint2(u.z, u.w);
            u = *reinterpret_cast<uint4*>(&vbh1);
            *reinterpret_cast<uint2*>(&Bs_hi[bn1 * BSTR + bkq])     = make_uint2(u.x, u.y);
            *reinterpret_cast<uint2*>(&Bs_hi[bn1 * BSTR + bkq + 4]) = make_uint2(u.z, u.w);
            u = *reinterpret_cast<uint4*>(&vbh2);
            *reinterpret_cast<uint2*>(&Bs_hi[bn2 * BSTR + bkq])     = make_uint2(u.x, u.y);
            *reinterpret_cast<uint2*>(&Bs_hi[bn2 * BSTR + bkq + 4]) = make_uint2(u.z, u.w);
            u = *reinterpret_cast<uint4*>(&vbh3);
            *reinterpret_cast<uint2*>(&Bs_hi[bn3 * BSTR + bkq])     = make_uint2(u.x, u.y);
            *reinterpret_cast<uint2*>(&Bs_hi[bn3 * BSTR + bkq + 4]) = make_uint2(u.z, u.w);
            u = *reinterpret_cast<uint4*>(&vbl0);
            *reinterpret_cast<uint2*>(&Bs_lo[bn0 * BSTR + bkq])     = make_uint2(u.x, u.y);
            *reinterpret_cast<uint2*>(&Bs_lo[bn0 * BSTR + bkq + 4]) = make_uint2(u.z, u.w);
            u = *reinterpret_cast<uint4*>(&vbl1);
            *reinterpret_cast<uint2*>(&Bs_lo[bn1 * BSTR + bkq])     = make_uint2(u.x, u.y);
            *reinterpret_cast<uint2*>(&Bs_lo[bn1 * BSTR + bkq + 4]) = make_uint2(u.z, u.w);
            u = *reinterpret_cast<uint4*>(&vbl2);
            *reinterpret_cast<uint2*>(&Bs_lo[bn2 * BSTR + bkq])     = make_uint2(u.x, u.y);
            *reinterpret_cast<uint2*>(&Bs_lo[bn2 * BSTR + bkq + 4]) = make_uint2(u.z, u.w);
            u = *reinterpret_cast<uint4*>(&vbl3);
            *reinterpret_cast<uint2*>(&Bs_lo[bn3 * BSTR + bkq])     = make_uint2(u.x, u.y);
            *reinterpret_cast<uint2*>(&Bs_lo[bn3 * BSTR + bkq + 4]) = make_uint2(u.z, u.w);
        }
        __syncthreads();

        // ---- compute: 2 k16-steps ----
        #pragma unroll
        for (int ks = 0; ks < 2; ks++) {
            int kk = ks * 16 + 2 * t;
            // B fragments [zh][nj][b0/b1]
            u32 bh[2][2][2], bl[2][2][2];
            #pragma unroll
            for (int zh = 0; zh < 2; zh++)
                #pragma unroll
                for (int nj = 0; nj < 2; nj++) {
                    int n = w * 16 + nj * 8 + g + zh * 128;
                    bh[zh][nj][0] = *reinterpret_cast<u32*>(&Bs_hi[n * BSTR + kk]);
                    bh[zh][nj][1] = *reinterpret_cast<u32*>(&Bs_hi[n * BSTR + kk + 8]);
                    bl[zh][nj][0] = *reinterpret_cast<u32*>(&Bs_lo[n * BSTR + kk]);
                    bl[zh][nj][1] = *reinterpret_cast<u32*>(&Bs_lo[n * BSTR + kk + 8]);
                }
            #pragma unroll
            for (int mi = 0; mi < 4; mi++) {
                int r = mi * 16 + g;
                u32 ah0 = *reinterpret_cast<u32*>(&As_hi[r * ASTR + kk]);
                u32 ah1 = *reinterpret_cast<u32*>(&As_hi[(r + 8) * ASTR + kk]);
                u32 ah2 = *reinterpret_cast<u32*>(&As_hi[r * ASTR + kk + 8]);
                u32 ah3 = *reinterpret_cast<u32*>(&As_hi[(r + 8) * ASTR + kk + 8]);
                u32 al0 = *reinterpret_cast<u32*>(&As_lo[r * ASTR + kk]);
                u32 al1 = *reinterpret_cast<u32*>(&As_lo[(r + 8) * ASTR + kk]);
                u32 al2 = *reinterpret_cast<u32*>(&As_lo[r * ASTR + kk + 8]);
                u32 al3 = *reinterpret_cast<u32*>(&As_lo[(r + 8) * ASTR + kk + 8]);
                #pragma unroll
                for (int zh = 0; zh < 2; zh++)
                    #pragma unroll
                    for (int nj = 0; nj < 2; nj++) {
                        MMA_BF16(acc[mi][zh][nj], ah0, ah1, ah2, ah3,
                                 bh[zh][nj][0], bh[zh][nj][1]);
                        MMA_BF16(acc[mi][zh][nj], ah0, ah1, ah2, ah3,
                                 bl[zh][nj][0], bl[zh][nj][1]);
                        MMA_BF16(acc[mi][zh][nj], al0, al1, al2, al3,
                                 bh[zh][nj][0], bh[zh][nj][1]);
                    }
            }
        }
    }

    // ---- fused gate epilogue ----
    #pragma unroll
    for (int nj = 0; nj < 2; nj++) {
        int col = w * 16 + nj * 8 + 2 * t;
        float bz0 = g_bias[col],       bz1 = g_bias[col + 1];
        float bh0 = g_bias[128 + col], bh1 = g_bias[129 + col];
        #pragma unroll
        for (int mi = 0; mi < 4; mi++) {
            int r0 = bm + mi * 16 + g;
            float* z = acc[mi][0][nj];
            float* h = acc[mi][1][nj];
            if (r0 < MROWS) {
                float2 o;
                o.x = (1.0f / (1.0f + expf(z[0] + bz0))) * tanhf(h[0] + bh0);
                o.y = (1.0f / (1.0f + expf(z[1] + bz1))) * tanhf(h[1] + bh1);
                *reinterpret_cast<float2*>(&out[(size_t)r0 * 128 + col]) = o;
            }
            int r1 = r0 + 8;
            if (r1 < MROWS) {
                float2 o;
                o.x = (1.0f / (1.0f + expf(z[2] + bz0))) * tanhf(h[2] + bh0);
                o.y = (1.0f / (1.0f + expf(z[3] + bz1))) * tanhf(h[3] + bh1);
                *reinterpret_cast<float2*>(&out[(size_t)r1 * 128 + col]) = o;
            }
        }
    }
}

extern "C" void kernel_launch(void* const* d_in, const int* in_sizes, int n_in,
                              void* d_out, int out_size) {
    const float* x  = (const float*)d_in[0];
    const int*   ei = (const int*)d_in[1];
    const float* ew = (const float*)d_in[2];
    const float* Wz = (const float*)d_in[3];
    const float* bz = (const float*)d_in[4];
    // d_in[5]=Wr, d_in[6]=br : dead (H0 == 0 => R multiplies zero)
    const float* Wh = (const float*)d_in[7];
    const float* bh = (const float*)d_in[8];
    float* out = (float*)d_out;

    k_zero   <<<(2 * NN + 255) / 256, 256>>>();
    k_degcnt <<<(NE + 255) / 256, 256>>>(ei, ew);
    k_scan   <<<1, 1024>>>();
    k_fill   <<<(NE + 255) / 256, 256>>>(ei, ew);
    k_weights<<<(KC * NC + 255) / 256, 256>>>(Wz, bz, Wh, bh);
    k_gather <<<(2 * NN * NB * 32 + 255) / 256, 256>>>(x);
    k_gemm   <<<MPAD / GBM, 256>>>(x, out);
}

// round 9
// speedup vs baseline: 2.0763x; 1.0167x over previous
#include <cuda_runtime.h>
#include <cuda_bf16.h>
#include <math.h>

// Problem constants (fixed shapes)
#define NB    4
#define NN    5000
#define NE    80000
#define MROWS 20000
#define MPAD  20096     // 314*64
#define KC    384       // [X | Txo | Txi]
#define NC    256       // [z | h]
#define SCAN_N (2*NN)

typedef unsigned int u32;

// -------- device scratch (static; zero-initialized at module load) --------
__device__ __align__(16) __nv_bfloat16 g_Xhi[(size_t)MPAD * 128];  // X split; pad rows stay 0
__device__ __align__(16) __nv_bfloat16 g_Xlo[(size_t)MPAD * 128];
__device__ __align__(16) __nv_bfloat16 g_Thi[(size_t)MPAD * 256];  // [Txo|Txi] split; pad rows stay 0
__device__ __align__(16) __nv_bfloat16 g_Tlo[(size_t)MPAD * 256];
__device__ __align__(16) __nv_bfloat16 g_Wt_hi[NC * KC];           // Wcat^T [n][k]
__device__ __align__(16) __nv_bfloat16 g_Wt_lo[NC * KC];
__device__ __align__(16) float g_bias[NC];
__device__ float g_deg[2 * NN];
__device__ int   g_cnt[SCAN_N];
__device__ int   g_off[SCAN_N + 1];
__device__ int   g_cursor[SCAN_N];
__device__ int   g_adj_nbr[2 * NE];
__device__ float g_adj_coef[2 * NE];

// -------- k1: weighted degrees + structural counts --------
// (g_deg/g_cnt are zero on entry: zero-init at load, re-zeroed by k_gather each run)
__global__ void k_degcnt(const int* __restrict__ ei, const float* __restrict__ ew) {
    int e = blockIdx.x * blockDim.x + threadIdx.x;
    if (e >= NE) return;
    int s = ei[e], d = ei[NE + e];
    float w = ew[e];
    atomicAdd(&g_deg[s], w);
    atomicAdd(&g_deg[NN + d], w);
    atomicAdd(&g_cnt[d], 1);
    atomicAdd(&g_cnt[NN + s], 1);
}

// -------- k2: exclusive scan via warp shuffles --------
__global__ void __launch_bounds__(1024) k_scan() {
    __shared__ int warp_sums[32];
    const int PER = 10;
    int t = threadIdx.x;
    int lane = t & 31, wid = t >> 5;
    int base = t * PER;
    int local[PER];
    int s = 0;
    #pragma unroll
    for (int i = 0; i < PER; i++) {
        int idx = base + i;
        int v = (idx < SCAN_N) ? g_cnt[idx] : 0;
        local[i] = s; s += v;
    }
    int sc = s;
    #pragma unroll
    for (int o = 1; o < 32; o <<= 1) {
        int u = __shfl_up_sync(0xFFFFFFFFu, sc, o);
        if (lane >= o) sc += u;
    }
    if (lane == 31) warp_sums[wid] = sc;
    __syncthreads();
    if (wid == 0) {
        int ws = warp_sums[lane];
        #pragma unroll
        for (int o = 1; o < 32; o <<= 1) {
            int u = __shfl_up_sync(0xFFFFFFFFu, ws, o);
            if (lane >= o) ws += u;
        }
        warp_sums[lane] = ws;
    }
    __syncthreads();
    int carry = (sc - s) + (wid > 0 ? warp_sums[wid - 1] : 0);
    #pragma unroll
    for (int i = 0; i < PER; i++) {
        int idx = base + i;
        if (idx < SCAN_N) {
            int o = carry + local[i];
            g_off[idx] = o;
            g_cursor[idx] = o;
        }
    }
    if (t == 1023) g_off[SCAN_N] = carry + s;
}

// -------- k3: fill adjacency; coefficients inline --------
__global__ void k_fill(const int* __restrict__ ei, const float* __restrict__ ew) {
    int e = blockIdx.x * blockDim.x + threadIdx.x;
    if (e >= NE) return;
    int s = ei[e], d = ei[NE + e];
    float w = ew[e];
    float dout = g_deg[s];
    float din  = g_deg[NN + d];
    int p = atomicAdd(&g_cursor[d], 1);
    g_adj_nbr[p]  = s;
    g_adj_coef[p] = (dout > 0.0f) ? w / dout : 0.0f;
    int q = atomicAdd(&g_cursor[NN + s], 1);
    g_adj_nbr[q]  = d;
    g_adj_coef[q] = (din > 0.0f) ? w / din : 0.0f;
}

// -------- bf16 split helper --------
__device__ __forceinline__ void split4(float4 v, uint2& uh, uint2& ul) {
    __nv_bfloat16 h0 = __float2bfloat16_rn(v.x);
    __nv_bfloat16 h1 = __float2bfloat16_rn(v.y);
    __nv_bfloat16 h2 = __float2bfloat16_rn(v.z);
    __nv_bfloat16 h3 = __float2bfloat16_rn(v.w);
    __nv_bfloat16 l0 = __float2bfloat16_rn(v.x - __bfloat162float(h0));
    __nv_bfloat16 l1 = __float2bfloat16_rn(v.y - __bfloat162float(h1));
    __nv_bfloat16 l2 = __float2bfloat16_rn(v.z - __bfloat162float(h2));
    __nv_bfloat16 l3 = __float2bfloat16_rn(v.w - __bfloat162float(h3));
    __nv_bfloat162 H0(h0, h1), H1(h2, h3), L0(l0, l1), L1(l2, l3);
    uh = make_uint2(*reinterpret_cast<u32*>(&H0), *reinterpret_cast<u32*>(&H1));
    ul = make_uint2(*reinterpret_cast<u32*>(&L0), *reinterpret_cast<u32*>(&L1));
}

// -------- k4: CSR gather diffusion -> bf16 hi/lo; also re-zeros g_deg/g_cnt --------
__global__ void k_gather(const float* __restrict__ x) {
    int gt = blockIdx.x * blockDim.x + threadIdx.x;
    if (gt < 2 * NN) { g_deg[gt] = 0.0f; g_cnt[gt] = 0; }  // reset for next replay

    int gw = gt >> 5;
    int lane = threadIdx.x & 31;
    if (gw >= 2 * NN * NB) return;
    int slot = gw >> 2;
    int b    = gw & 3;
    int half = slot / NN;
    int v    = slot % NN;

    int beg = g_off[slot];
    int end = g_off[slot + 1];

    const float4* X4 = reinterpret_cast<const float4*>(x) + (size_t)b * NN * 32;
    float4 acc = make_float4(0.f, 0.f, 0.f, 0.f);

    int p = beg;
    for (; p + 4 <= end; p += 4) {
        int   n0 = g_adj_nbr[p],     n1 = g_adj_nbr[p + 1];
        int   n2 = g_adj_nbr[p + 2], n3 = g_adj_nbr[p + 3];
        float c0 = g_adj_coef[p],     c1 = g_adj_coef[p + 1];
        float c2 = g_adj_coef[p + 2], c3 = g_adj_coef[p + 3];
        float4 x0 = X4[(size_t)n0 * 32 + lane];
        float4 x1 = X4[(size_t)n1 * 32 + lane];
        float4 x2 = X4[(size_t)n2 * 32 + lane];
        float4 x3 = X4[(size_t)n3 * 32 + lane];
        acc.x = fmaf(c0, x0.x, acc.x); acc.y = fmaf(c0, x0.y, acc.y);
        acc.z = fmaf(c0, x0.z, acc.z); acc.w = fmaf(c0, x0.w, acc.w);
        acc.x = fmaf(c1, x1.x, acc.x); acc.y = fmaf(c1, x1.y, acc.y);
        acc.z = fmaf(c1, x1.z, acc.z); acc.w = fmaf(c1, x1.w, acc.w);
        acc.x = fmaf(c2, x2.x, acc.x); acc.y = fmaf(c2, x2.y, acc.y);
        acc.z = fmaf(c2, x2.z, acc.z); acc.w = fmaf(c2, x2.w, acc.w);
        acc.x = fmaf(c3, x3.x, acc.x); acc.y = fmaf(c3, x3.y, acc.y);
        acc.z = fmaf(c3, x3.z, acc.z); acc.w = fmaf(c3, x3.w, acc.w);
    }
    for (; p < end; p++) {
        int   n0 = g_adj_nbr[p];
        float c0 = g_adj_coef[p];
        float4 x0 = X4[(size_t)n0 * 32 + lane];
        acc.x = fmaf(c0, x0.x, acc.x); acc.y = fmaf(c0, x0.y, acc.y);
        acc.z = fmaf(c0, x0.z, acc.z); acc.w = fmaf(c0, x0.w, acc.w);
    }

    uint2 uh, ul;
    split4(acc, uh, ul);
    size_t idx = (size_t)(b * NN + v) * 64 + half * 32 + lane;  // uint2 units (row = 64)
    reinterpret_cast<uint2*>(g_Thi)[idx] = uh;
    reinterpret_cast<uint2*>(g_Tlo)[idx] = ul;
}

// -------- k5: split X -> bf16 hi/lo --------
__global__ void k_xconv(const float* __restrict__ x) {
    int i = blockIdx.x * blockDim.x + threadIdx.x;   // float4 index over [MROWS,128]
    if (i >= MROWS * 32) return;
    float4 v = reinterpret_cast<const float4*>(x)[i];
    uint2 uh, ul;
    split4(v, uh, ul);
    reinterpret_cast<uint2*>(g_Xhi)[i] = uh;
    reinterpret_cast<uint2*>(g_Xlo)[i] = ul;
}

// -------- k6: stacked weights -> transposed bf16 hi/lo + bias --------
__global__ void k_weights(const float* __restrict__ Wz, const float* __restrict__ bz,
                          const float* __restrict__ Wh, const float* __restrict__ bh) {
    int id = blockIdx.x * blockDim.x + threadIdx.x;
    if (id >= KC * NC) return;
    int k = id / NC;
    int j = id % NC;
    const float* W = (j < 128) ? Wz : Wh;
    int jc = j & 127;
    float v;
    if (k < 128)      v = W[k * 128 + jc] + W[(512 + k) * 128 + jc];
    else if (k < 256) v = W[(256 + (k - 128)) * 128 + jc];
    else              v = W[(768 + (k - 256)) * 128 + jc];
    __nv_bfloat16 hi = __float2bfloat16_rn(v);
    __nv_bfloat16 lo = __float2bfloat16_rn(v - __bfloat162float(hi));
    g_Wt_hi[j * KC + k] = hi;
    g_Wt_lo[j * KC + k] = lo;
    if (id < NC) g_bias[id] = (id < 128) ? bz[id] : bh[id - 128];
}

// -------- k7: cp.async double-buffered bf16x3 tensor GEMM + fused gate epilogue --------
#define GBM 64
#define GBK 32
#define NITER (KC / GBK)     // 12
#define ASTR 40
#define BSTR 40
#define A_ELEMS (GBM * ASTR)          // 2560 bf16
#define B_ELEMS (NC * BSTR)           // 10240 bf16
#define STAGE_ELEMS (2 * A_ELEMS + 2 * B_ELEMS)   // 25600 bf16
#define SMEM_BYTES (2 * STAGE_ELEMS * 2)          // 102400 B

#define MMA_BF16(c, a0, a1, a2, a3, b0, b1)                                \
    asm("mma.sync.aligned.m16n8k16.row.col.f32.bf16.bf16.f32 "             \
        "{%0,%1,%2,%3}, {%4,%5,%6,%7}, {%8,%9}, {%0,%1,%2,%3};"            \
        : "+f"((c)[0]), "+f"((c)[1]), "+f"((c)[2]), "+f"((c)[3])           \
        : "r"(a0), "r"(a1), "r"(a2), "r"(a3), "r"(b0), "r"(b1))

__device__ __forceinline__ void cpa16(__nv_bfloat16* dst, const __nv_bfloat16* src) {
    u32 d = (u32)__cvta_generic_to_shared(dst);
    asm volatile("cp.async.cg.shared.global [%0], [%1], 16;" :: "r"(d), "l"(src));
}

__device__ __forceinline__ void issue_stage(__nv_bfloat16* sm, int stage, int k0,
                                            int bm, int tid) {
    __nv_bfloat16* Ah = sm + stage * STAGE_ELEMS;
    __nv_bfloat16* Al = Ah + A_ELEMS;
    __nv_bfloat16* Bh = Al + A_ELEMS;
    __nv_bfloat16* Bl = Bh + B_ELEMS;
    // A: 512 16B-chunks (hi+lo), 2 per thread
    #pragma unroll
    for (int j = 0; j < 2; j++) {
        int c = tid + j * 256;
        int mat = c >> 8;
        int rr  = (c & 255) >> 2;
        int q   = c & 3;
        const __nv_bfloat16* src;
        if (k0 < 128) {
            const __nv_bfloat16* base = mat ? g_Xlo : g_Xhi;
            src = base + (size_t)(bm + rr) * 128 + k0 + q * 8;
        } else {
            const __nv_bfloat16* base = mat ? g_Tlo : g_Thi;
            src = base + (size_t)(bm + rr) * 256 + (k0 - 128) + q * 8;
        }
        cpa16((mat ? Al : Ah) + rr * ASTR + q * 8, src);
    }
    // B: 2048 chunks (hi+lo), 8 per thread
    #pragma unroll
    for (int j = 0; j < 8; j++) {
        int c = tid + j * 256;
        int mat = c >> 10;
        int n   = (c >> 2) & 255;
        int q   = c & 3;
        const __nv_bfloat16* src = (mat ? g_Wt_lo : g_Wt_hi) + n * KC + k0 + q * 8;
        cpa16((mat ? Bl : Bh) + n * BSTR + q * 8, src);
    }
    asm volatile("cp.async.commit_group;");
}

__global__ void __launch_bounds__(256) k_gemm(float* __restrict__ out) {
    extern __shared__ __align__(16) __nv_bfloat16 sm[];
    int tid = threadIdx.x;
    int w = tid >> 5, lane = tid & 31;
    int g = lane >> 2, t = lane & 3;
    int bm = blockIdx.x * GBM;

    float acc[4][2][2][4];
    #pragma unroll
    for (int mi = 0; mi < 4; mi++)
        #pragma unroll
        for (int zh = 0; zh < 2; zh++)
            #pragma unroll
            for (int nj = 0; nj < 2; nj++)
                #pragma unroll
                for (int q = 0; q < 4; q++) acc[mi][zh][nj][q] = 0.f;

    issue_stage(sm, 0, 0, bm, tid);

    for (int it = 0; it < NITER; it++) {
        if (it + 1 < NITER) {
            issue_stage(sm, (it + 1) & 1, (it + 1) * GBK, bm, tid);
            asm volatile("cp.async.wait_group 1;");
        } else {
            asm volatile("cp.async.wait_group 0;");
        }
        __syncthreads();

        const __nv_bfloat16* Ah = sm + (it & 1) * STAGE_ELEMS;
        const __nv_bfloat16* Al = Ah + A_ELEMS;
        const __nv_bfloat16* Bh = Al + A_ELEMS;
        const __nv_bfloat16* Bl = Bh + B_ELEMS;

        #pragma unroll
        for (int ks = 0; ks < 2; ks++) {
            int kk = ks * 16 + 2 * t;
            u32 bhf[2][2][2], blf[2][2][2];
            #pragma unroll
            for (int zh = 0; zh < 2; zh++)
                #pragma unroll
                for (int nj = 0; nj < 2; nj++) {
                    int n = w * 16 + nj * 8 + g + zh * 128;
                    bhf[zh][nj][0] = *reinterpret_cast<const u32*>(&Bh[n * BSTR + kk]);
                    bhf[zh][nj][1] = *reinterpret_cast<const u32*>(&Bh[n * BSTR + kk + 8]);
                    blf[zh][nj][0] = *reinterpret_cast<const u32*>(&Bl[n * BSTR + kk]);
                    blf[zh][nj][1] = *reinterpret_cast<const u32*>(&Bl[n * BSTR + kk + 8]);
                }
            #pragma unroll
            for (int mi = 0; mi < 4; mi++) {
                int r = mi * 16 + g;
                u32 ah0 = *reinterpret_cast<const u32*>(&Ah[r * ASTR + kk]);
                u32 ah1 = *reinterpret_cast<const u32*>(&Ah[(r + 8) * ASTR + kk]);
                u32 ah2 = *reinterpret_cast<const u32*>(&Ah[r * ASTR + kk + 8]);
                u32 ah3 = *reinterpret_cast<const u32*>(&Ah[(r + 8) * ASTR + kk + 8]);
                u32 al0 = *reinterpret_cast<const u32*>(&Al[r * ASTR + kk]);
                u32 al1 = *reinterpret_cast<const u32*>(&Al[(r + 8) * ASTR + kk]);
                u32 al2 = *reinterpret_cast<const u32*>(&Al[r * ASTR + kk + 8]);
                u32 al3 = *reinterpret_cast<const u32*>(&Al[(r + 8) * ASTR + kk + 8]);
                #pragma unroll
                for (int zh = 0; zh < 2; zh++)
                    #pragma unroll
                    for (int nj = 0; nj < 2; nj++) {
                        MMA_BF16(acc[mi][zh][nj], ah0, ah1, ah2, ah3,
                                 bhf[zh][nj][0], bhf[zh][nj][1]);
                        MMA_BF16(acc[mi][zh][nj], ah0, ah1, ah2, ah3,
                                 blf[zh][nj][0], blf[zh][nj][1]);
                        MMA_BF16(acc[mi][zh][nj], al0, al1, al2, al3,
                                 bhf[zh][nj][0], bhf[zh][nj][1]);
                    }
            }
        }
        __syncthreads();
    }

    // ---- fused gate epilogue ----
    #pragma unroll
    for (int nj = 0; nj < 2; nj++) {
        int col = w * 16 + nj * 8 + 2 * t;
        float bz0 = g_bias[col],       bz1 = g_bias[col + 1];
        float bh0 = g_bias[128 + col], bh1 = g_bias[129 + col];
        #pragma unroll
        for (int mi = 0; mi < 4; mi++) {
            int r0 = bm + mi * 16 + g;
            float* z = acc[mi][0][nj];
            float* h = acc[mi][1][nj];
            if (r0 < MROWS) {
                float2 o;
                o.x = (1.0f / (1.0f + expf(z[0] + bz0))) * tanhf(h[0] + bh0);
                o.y = (1.0f / (1.0f + expf(z[1] + bz1))) * tanhf(h[1] + bh1);
                *reinterpret_cast<float2*>(&out[(size_t)r0 * 128 + col]) = o;
            }
            int r1 = r0 + 8;
            if (r1 < MROWS) {
                float2 o;
                o.x = (1.0f / (1.0f + expf(z[2] + bz0))) * tanhf(h[2] + bh0);
                o.y = (1.0f / (1.0f + expf(z[3] + bz1))) * tanhf(h[3] + bh1);
                *reinterpret_cast<float2*>(&out[(size_t)r1 * 128 + col]) = o;
            }
        }
    }
}

extern "C" void kernel_launch(void* const* d_in, const int* in_sizes, int n_in,
                              void* d_out, int out_size) {
    const float* x  = (const float*)d_in[0];
    const int*   ei = (const int*)d_in[1];
    const float* ew = (const float*)d_in[2];
    const float* Wz = (const float*)d_in[3];
    const float* bz = (const float*)d_in[4];
    // d_in[5]=Wr, d_in[6]=br : dead (H0 == 0 => R multiplies zero)
    const float* Wh = (const float*)d_in[7];
    const float* bh = (const float*)d_in[8];
    float* out = (float*)d_out;

    cudaFuncSetAttribute(k_gemm, cudaFuncAttributeMaxDynamicSharedMemorySize, SMEM_BYTES);

    k_degcnt <<<(NE + 255) / 256, 256>>>(ei, ew);               // #1
    k_scan   <<<1, 1024>>>();                                   // #2
    k_fill   <<<(NE + 255) / 256, 256>>>(ei, ew);               // #3
    k_gather <<<(2 * NN * NB * 32 + 255) / 256, 256>>>(x);      // #4  <- ncu sample slot
    k_xconv  <<<(MROWS * 32 + 255) / 256, 256>>>(x);            // #5
    k_weights<<<(KC * NC + 255) / 256, 256>>>(Wz, bz, Wh, bh);  // #6
    k_gemm   <<<MPAD / GBM, 256, SMEM_BYTES>>>(out);            // #7
}

// round 11
// speedup vs baseline: 2.6062x; 1.2552x over previous
#include <cuda_runtime.h>
#include <cuda_fp16.h>
#include <math.h>

// Problem constants (fixed shapes)
#define NB    4
#define NN    5000
#define NE    80000
#define MROWS 20000
#define MPAD  20096     // 314*64
#define KC    384       // [X | Txo | Txi]
#define NC    256       // [z | h]
#define SCAN_N (2*NN)

typedef unsigned int u32;

// -------- device scratch (static; zero-initialized at module load) --------
__device__ __align__(16) __half g_Xhi[(size_t)MPAD * 128];  // pad rows stay 0
__device__ __align__(16) __half g_Xlo[(size_t)MPAD * 128];
__device__ __align__(16) __half g_Thi[(size_t)MPAD * 256];  // [Txo|Txi]; pad rows stay 0
__device__ __align__(16) __half g_Tlo[(size_t)MPAD * 256];
__device__ __align__(16) __half g_Wt[NC * KC];              // Wcat^T [n][k], single fp16
__device__ __align__(16) float g_bias[NC];
__device__ float g_deg[2 * NN];
__device__ int   g_cnt[SCAN_N];
__device__ int   g_off[SCAN_N + 1];
__device__ int   g_cursor[SCAN_N];
__device__ int   g_adj_nbr[2 * NE];
__device__ float g_adj_coef[2 * NE];

// -------- k1: weighted degrees + structural counts --------
__global__ void k_degcnt(const int* __restrict__ ei, const float* __restrict__ ew) {
    int e = blockIdx.x * blockDim.x + threadIdx.x;
    if (e >= NE) return;
    int s = ei[e], d = ei[NE + e];
    float w = ew[e];
    atomicAdd(&g_deg[s], w);
    atomicAdd(&g_deg[NN + d], w);
    atomicAdd(&g_cnt[d], 1);
    atomicAdd(&g_cnt[NN + s], 1);
}

// -------- k2: exclusive scan via warp shuffles --------
__global__ void __launch_bounds__(1024) k_scan() {
    __shared__ int warp_sums[32];
    const int PER = 10;
    int t = threadIdx.x;
    int lane = t & 31, wid = t >> 5;
    int base = t * PER;
    int local[PER];
    int s = 0;
    #pragma unroll
    for (int i = 0; i < PER; i++) {
        int idx = base + i;
        int v = (idx < SCAN_N) ? g_cnt[idx] : 0;
        local[i] = s; s += v;
    }
    int sc = s;
    #pragma unroll
    for (int o = 1; o < 32; o <<= 1) {
        int u = __shfl_up_sync(0xFFFFFFFFu, sc, o);
        if (lane >= o) sc += u;
    }
    if (lane == 31) warp_sums[wid] = sc;
    __syncthreads();
    if (wid == 0) {
        int ws = warp_sums[lane];
        #pragma unroll
        for (int o = 1; o < 32; o <<= 1) {
            int u = __shfl_up_sync(0xFFFFFFFFu, ws, o);
            if (lane >= o) ws += u;
        }
        warp_sums[lane] = ws;
    }
    __syncthreads();
    int carry = (sc - s) + (wid > 0 ? warp_sums[wid - 1] : 0);
    #pragma unroll
    for (int i = 0; i < PER; i++) {
        int idx = base + i;
        if (idx < SCAN_N) {
            int o = carry + local[i];
            g_off[idx] = o;
            g_cursor[idx] = o;
        }
    }
    if (t == 1023) g_off[SCAN_N] = carry + s;
}

// -------- k3: fill adjacency; coefficients inline --------
__global__ void k_fill(const int* __restrict__ ei, const float* __restrict__ ew) {
    int e = blockIdx.x * blockDim.x + threadIdx.x;
    if (e >= NE) return;
    int s = ei[e], d = ei[NE + e];
    float w = ew[e];
    float dout = g_deg[s];
    float din  = g_deg[NN + d];
    int p = atomicAdd(&g_cursor[d], 1);
    g_adj_nbr[p]  = s;
    g_adj_coef[p] = (dout > 0.0f) ? w / dout : 0.0f;
    int q = atomicAdd(&g_cursor[NN + s], 1);
    g_adj_nbr[q]  = d;
    g_adj_coef[q] = (din > 0.0f) ? w / din : 0.0f;
}

// -------- fp16 hi/lo split helper: float4 -> 4 hi halves + 4 lo halves --------
__device__ __forceinline__ void split4h(float4 v, uint2& uh, uint2& ul) {
    __half h0 = __float2half_rn(v.x);
    __half h1 = __float2half_rn(v.y);
    __half h2 = __float2half_rn(v.z);
    __half h3 = __float2half_rn(v.w);
    __half l0 = __float2half_rn(v.x - __half2float(h0));
    __half l1 = __float2half_rn(v.y - __half2float(h1));
    __half l2 = __float2half_rn(v.z - __half2float(h2));
    __half l3 = __float2half_rn(v.w - __half2float(h3));
    __half2 H0(h0, h1), H1(h2, h3), L0(l0, l1), L1(l2, l3);
    uh = make_uint2(*reinterpret_cast<u32*>(&H0), *reinterpret_cast<u32*>(&H1));
    ul = make_uint2(*reinterpret_cast<u32*>(&L0), *reinterpret_cast<u32*>(&L1));
}

// -------- k4: fused: CSR gather + X split + weight convert + state reset --------
__global__ void k_gather(const float* __restrict__ x,
                         const float* __restrict__ Wz, const float* __restrict__ bz,
                         const float* __restrict__ Wh, const float* __restrict__ bh) {
    int gt = blockIdx.x * blockDim.x + threadIdx.x;

    // fused A: reset degree/count state for next replay
    if (gt < 2 * NN) { g_deg[gt] = 0.0f; g_cnt[gt] = 0; }

    // fused B: weights -> transposed single fp16 + bias
    if (gt < KC * NC) {
        int k = gt / NC;
        int j = gt % NC;
        const float* W = (j < 128) ? Wz : Wh;
        int jc = j & 127;
        float v;
        if (k < 128)      v = W[k * 128 + jc] + W[(512 + k) * 128 + jc];
        else if (k < 256) v = W[(256 + (k - 128)) * 128 + jc];
        else              v = W[(768 + (k - 256)) * 128 + jc];
        g_Wt[j * KC + k] = __float2half_rn(v);
        if (gt < NC) g_bias[gt] = (gt < 128) ? bz[gt] : bh[gt - 128];
    }

    // fused C: X -> fp16 hi/lo split (one float4 per thread)
    if (gt < MROWS * 32) {
        float4 v = reinterpret_cast<const float4*>(x)[gt];
        uint2 uh, ul;
        split4h(v, uh, ul);
        reinterpret_cast<uint2*>(g_Xhi)[gt] = uh;
        reinterpret_cast<uint2*>(g_Xlo)[gt] = ul;
    }

    // main: CSR gather, one warp per (slot, batch)
    int gw = gt >> 5;
    int lane = threadIdx.x & 31;
    if (gw >= 2 * NN * NB) return;
    int slot = gw >> 2;
    int b    = gw & 3;
    int half = slot / NN;
    int v    = slot % NN;

    int beg = g_off[slot];
    int end = g_off[slot + 1];

    const float4* X4 = reinterpret_cast<const float4*>(x) + (u32)b * (u32)NN * 32u;
    float4 acc = make_float4(0.f, 0.f, 0.f, 0.f);

    int p = beg;
    for (; p + 4 <= end; p += 4) {
        int   n0 = g_adj_nbr[p],     n1 = g_adj_nbr[p + 1];
        int   n2 = g_adj_nbr[p + 2], n3 = g_adj_nbr[p + 3];
        float c0 = g_adj_coef[p],     c1 = g_adj_coef[p + 1];
        float c2 = g_adj_coef[p + 2], c3 = g_adj_coef[p + 3];
        float4 x0 = X4[(u32)n0 * 32u + lane];
        float4 x1 = X4[(u32)n1 * 32u + lane];
        float4 x2 = X4[(u32)n2 * 32u + lane];
        float4 x3 = X4[(u32)n3 * 32u + lane];
        acc.x = fmaf(c0, x0.x, acc.x); acc.y = fmaf(c0, x0.y, acc.y);
        acc.z = fmaf(c0, x0.z, acc.z); acc.w = fmaf(c0, x0.w, acc.w);
        acc.x = fmaf(c1, x1.x, acc.x); acc.y = fmaf(c1, x1.y, acc.y);
        acc.z = fmaf(c1, x1.z, acc.z); acc.w = fmaf(c1, x1.w, acc.w);
        acc.x = fmaf(c2, x2.x, acc.x); acc.y = fmaf(c2, x2.y, acc.y);
        acc.z = fmaf(c2, x2.z, acc.z); acc.w = fmaf(c2, x2.w, acc.w);
        acc.x = fmaf(c3, x3.x, acc.x); acc.y = fmaf(c3, x3.y, acc.y);
        acc.z = fmaf(c3, x3.z, acc.z); acc.w = fmaf(c3, x3.w, acc.w);
    }
    for (; p < end; p++) {
        int   n0 = g_adj_nbr[p];
        float c0 = g_adj_coef[p];
        float4 x0 = X4[(u32)n0 * 32u + lane];
        acc.x = fmaf(c0, x0.x, acc.x); acc.y = fmaf(c0, x0.y, acc.y);
        acc.z = fmaf(c0, x0.z, acc.z); acc.w = fmaf(c0, x0.w, acc.w);
    }

    uint2 uh, ul;
    split4h(acc, uh, ul);
    u32 idx = (u32)(b * NN + v) * 64u + (u32)half * 32u + (u32)lane;  // uint2 units
    reinterpret_cast<uint2*>(g_Thi)[idx] = uh;
    reinterpret_cast<uint2*>(g_Tlo)[idx] = ul;
}

// -------- k5: cp.async double-buffered fp16x2 tensor GEMM + fused gate epilogue --------
#define GBM 64
#define GBK 32
#define NITER (KC / GBK)     // 12
#define ASTR 40
#define BSTR 40
#define A_ELEMS (GBM * ASTR)                     // 2560 halves
#define B_ELEMS (NC * BSTR)                      // 10240 halves
#define STAGE_ELEMS (2 * A_ELEMS + B_ELEMS)      // 15360 halves
#define SMEM_BYTES (2 * STAGE_ELEMS * 2)         // 61440 B

#define MMA_F16(c, a0, a1, a2, a3, b0, b1)                                 \
    asm("mma.sync.aligned.m16n8k16.row.col.f32.f16.f16.f32 "               \
        "{%0,%1,%2,%3}, {%4,%5,%6,%7}, {%8,%9}, {%0,%1,%2,%3};"            \
        : "+f"((c)[0]), "+f"((c)[1]), "+f"((c)[2]), "+f"((c)[3])           \
        : "r"(a0), "r"(a1), "r"(a2), "r"(a3), "r"(b0), "r"(b1))

__device__ __forceinline__ void cpa16(__half* dst, const __half* src) {
    u32 d = (u32)__cvta_generic_to_shared(dst);
    asm volatile("cp.async.cg.shared.global [%0], [%1], 16;" :: "r"(d), "l"(src));
}

__device__ __forceinline__ void issue_stage(__half* sm, int stage, int k0,
                                            int bm, int tid) {
    __half* Ah = sm + stage * STAGE_ELEMS;
    __half* Al = Ah + A_ELEMS;
    __half* Bs = Al + A_ELEMS;
    // A: 512 16B-chunks (hi+lo), 2 per thread. chunk c: mat=c>>8, row=(c&255)>>2, q=c&3
    #pragma unroll
    for (int j = 0; j < 2; j++) {
        int c = tid + j * 256;
        int mat = c >> 8;
        int rr  = (c & 255) >> 2;
        int q   = c & 3;
        const __half* src;
        if (k0 < 128) {
            const __half* base = mat ? g_Xlo : g_Xhi;
            src = base + (size_t)(bm + rr) * 128 + k0 + q * 8;
        } else {
            const __half* base = mat ? g_Tlo : g_Thi;
            src = base + (size_t)(bm + rr) * 256 + (k0 - 128) + q * 8;
        }
        cpa16((mat ? Al : Ah) + rr * ASTR + q * 8, src);
    }
    // B: 1024 chunks, 4 per thread. chunk c: n=c>>2, q=c&3
    #pragma unroll
    for (int j = 0; j < 4; j++) {
        int c = tid + j * 256;
        int n = c >> 2;
        int q = c & 3;
        cpa16(Bs + n * BSTR + q * 8, g_Wt + n * KC + k0 + q * 8);
    }
    asm volatile("cp.async.commit_group;");
}

__global__ void __launch_bounds__(256) k_gemm(float* __restrict__ out) {
    extern __shared__ __align__(16) __half sm[];
    int tid = threadIdx.x;
    int w = tid >> 5, lane = tid & 31;
    int g = lane >> 2, t = lane & 3;
    int bm = blockIdx.x * GBM;

    float acc[4][2][2][4];
    #pragma unroll
    for (int mi = 0; mi < 4; mi++)
        #pragma unroll
        for (int zh = 0; zh < 2; zh++)
            #pragma unroll
            for (int nj = 0; nj < 2; nj++)
                #pragma unroll
                for (int q = 0; q < 4; q++) acc[mi][zh][nj][q] = 0.f;

    issue_stage(sm, 0, 0, bm, tid);

    for (int it = 0; it < NITER; it++) {
        if (it + 1 < NITER) {
            issue_stage(sm, (it + 1) & 1, (it + 1) * GBK, bm, tid);
            asm volatile("cp.async.wait_group 1;");
        } else {
            asm volatile("cp.async.wait_group 0;");
        }
        __syncthreads();

        const __half* Ah = sm + (it & 1) * STAGE_ELEMS;
        const __half* Al = Ah + A_ELEMS;
        const __half* Bs = Al + A_ELEMS;

        #pragma unroll
        for (int ks = 0; ks < 2; ks++) {
            int kk = ks * 16 + 2 * t;
            u32 bf[2][2][2];
            #pragma unroll
            for (int zh = 0; zh < 2; zh++)
                #pragma unroll
                for (int nj = 0; nj < 2; nj++) {
                    int n = w * 16 + nj * 8 + g + zh * 128;
                    bf[zh][nj][0] = *reinterpret_cast<const u32*>(&Bs[n * BSTR + kk]);
                    bf[zh][nj][1] = *reinterpret_cast<const u32*>(&Bs[n * BSTR + kk + 8]);
                }
            #pragma unroll
            for (int mi = 0; mi < 4; mi++) {
                int r = mi * 16 + g;
                u32 ah0 = *reinterpret_cast<const u32*>(&Ah[r * ASTR + kk]);
                u32 ah1 = *reinterpret_cast<const u32*>(&Ah[(r + 8) * ASTR + kk]);
                u32 ah2 = *reinterpret_cast<const u32*>(&Ah[r * ASTR + kk + 8]);
                u32 ah3 = *reinterpret_cast<const u32*>(&Ah[(r + 8) * ASTR + kk + 8]);
                u32 al0 = *reinterpret_cast<const u32*>(&Al[r * ASTR + kk]);
                u32 al1 = *reinterpret_cast<const u32*>(&Al[(r + 8) * ASTR + kk]);
                u32 al2 = *reinterpret_cast<const u32*>(&Al[r * ASTR + kk + 8]);
                u32 al3 = *reinterpret_cast<const u32*>(&Al[(r + 8) * ASTR + kk + 8]);
                #pragma unroll
                for (int zh = 0; zh < 2; zh++)
                    #pragma unroll
                    for (int nj = 0; nj < 2; nj++) {
                        MMA_F16(acc[mi][zh][nj], ah0, ah1, ah2, ah3,
                                bf[zh][nj][0], bf[zh][nj][1]);
                        MMA_F16(acc[mi][zh][nj], al0, al1, al2, al3,
                                bf[zh][nj][0], bf[zh][nj][1]);
                    }
            }
        }
        __syncthreads();
    }

    // ---- fused gate epilogue ----
    #pragma unroll
    for (int nj = 0; nj < 2; nj++) {
        int col = w * 16 + nj * 8 + 2 * t;
        float bz0 = g_bias[col],       bz1 = g_bias[col + 1];
        float bh0 = g_bias[128 + col], bh1 = g_bias[129 + col];
        #pragma unroll
        for (int mi = 0; mi < 4; mi++) {
            int r0 = bm + mi * 16 + g;
            float* z = acc[mi][0][nj];
            float* h = acc[mi][1][nj];
            if (r0 < MROWS) {
                float2 o;
                o.x = (1.0f / (1.0f + expf(z[0] + bz0))) * tanhf(h[0] + bh0);
                o.y = (1.0f / (1.0f + expf(z[1] + bz1))) * tanhf(h[1] + bh1);
                *reinterpret_cast<float2*>(&out[(size_t)r0 * 128 + col]) = o;
            }
            int r1 = r0 + 8;
            if (r1 < MROWS) {
                float2 o;
                o.x = (1.0f / (1.0f + expf(z[2] + bz0))) * tanhf(h[2] + bh0);
                o.y = (1.0f / (1.0f + expf(z[3] + bz1))) * tanhf(h[3] + bh1);
                *reinterpret_cast<float2*>(&out[(size_t)r1 * 128 + col]) = o;
            }
        }
    }
}

extern "C" void kernel_launch(void* const* d_in, const int* in_sizes, int n_in,
                              void* d_out, int out_size) {
    const float* x  = (const float*)d_in[0];
    const int*   ei = (const int*)d_in[1];
    const float* ew = (const float*)d_in[2];
    const float* Wz = (const float*)d_in[3];
    const float* bz = (const float*)d_in[4];
    // d_in[5]=Wr, d_in[6]=br : dead (H0 == 0 => R multiplies zero)
    const float* Wh = (const float*)d_in[7];
    const float* bh = (const float*)d_in[8];
    float* out = (float*)d_out;

    cudaFuncSetAttribute(k_gemm, cudaFuncAttributeMaxDynamicSharedMemorySize, SMEM_BYTES);

    k_degcnt <<<(NE + 255) / 256, 256>>>(ei, ew);                          // #1
    k_scan   <<<1, 1024>>>();                                              // #2
    k_fill   <<<(NE + 255) / 256, 256>>>(ei, ew);                          // #3
    k_gather <<<(2 * NN * NB * 32 + 255) / 256, 256>>>(x, Wz, bz, Wh, bh); // #4
    k_gemm   <<<MPAD / GBM, 256, SMEM_BYTES>>>(out);                       // #5
}

// round 12
// speedup vs baseline: 3.0633x; 1.1754x over previous
#include <cuda_runtime.h>
#include <cuda_fp16.h>
#include <math.h>

// Problem constants (fixed shapes)
#define NB    4
#define NN    5000
#define NE    80000
#define MROWS 20000
#define MPAD  20096     // 314*64
#define KC    384       // [X | Txo | Txi]
#define NC    256       // [z | h]
#define SCAN_N (2*NN)

typedef unsigned int u32;

// -------- device scratch (static; zero-initialized at module load) --------
__device__ __align__(16) __half g_Xh[(size_t)MPAD * 128];   // X fp16; pad rows stay 0
__device__ __align__(16) __half g_Th[(size_t)MPAD * 256];   // [Txo|Txi] fp16; pad rows stay 0
__device__ __align__(16) __half g_Wt[NC * KC];              // Wcat^T [n][k] fp16
__device__ __align__(16) float g_bias[NC];
__device__ float g_deg[2 * NN];
__device__ int   g_cnt[SCAN_N];
__device__ int   g_off[SCAN_N + 1];
__device__ int   g_cursor[SCAN_N];
__device__ int   g_adj_nbr[2 * NE];
__device__ float g_adj_coef[2 * NE];

// -------- k1: weighted degrees + structural counts --------
__global__ void k_degcnt(const int* __restrict__ ei, const float* __restrict__ ew) {
    int e = blockIdx.x * blockDim.x + threadIdx.x;
    if (e >= NE) return;
    int s = ei[e], d = ei[NE + e];
    float w = ew[e];
    atomicAdd(&g_deg[s], w);
    atomicAdd(&g_deg[NN + d], w);
    atomicAdd(&g_cnt[d], 1);
    atomicAdd(&g_cnt[NN + s], 1);
}

// -------- k2: exclusive scan via warp shuffles --------
__global__ void __launch_bounds__(1024) k_scan() {
    __shared__ int warp_sums[32];
    const int PER = 10;
    int t = threadIdx.x;
    int lane = t & 31, wid = t >> 5;
    int base = t * PER;
    int local[PER];
    int s = 0;
    #pragma unroll
    for (int i = 0; i < PER; i++) {
        int idx = base + i;
        int v = (idx < SCAN_N) ? g_cnt[idx] : 0;
        local[i] = s; s += v;
    }
    int sc = s;
    #pragma unroll
    for (int o = 1; o < 32; o <<= 1) {
        int u = __shfl_up_sync(0xFFFFFFFFu, sc, o);
        if (lane >= o) sc += u;
    }
    if (lane == 31) warp_sums[wid] = sc;
    __syncthreads();
    if (wid == 0) {
        int ws = warp_sums[lane];
        #pragma unroll
        for (int o = 1; o < 32; o <<= 1) {
            int u = __shfl_up_sync(0xFFFFFFFFu, ws, o);
            if (lane >= o) ws += u;
        }
        warp_sums[lane] = ws;
    }
    __syncthreads();
    int carry = (sc - s) + (wid > 0 ? warp_sums[wid - 1] : 0);
    #pragma unroll
    for (int i = 0; i < PER; i++) {
        int idx = base + i;
        if (idx < SCAN_N) {
            int o = carry + local[i];
            g_off[idx] = o;
            g_cursor[idx] = o;
        }
    }
    if (t == 1023) g_off[SCAN_N] = carry + s;
}

// -------- k3: fill adjacency; coefficients inline --------
__global__ void k_fill(const int* __restrict__ ei, const float* __restrict__ ew) {
    int e = blockIdx.x * blockDim.x + threadIdx.x;
    if (e >= NE) return;
    int s = ei[e], d = ei[NE + e];
    float w = ew[e];
    float dout = g_deg[s];
    float din  = g_deg[NN + d];
    int p = atomicAdd(&g_cursor[d], 1);
    g_adj_nbr[p]  = s;
    g_adj_coef[p] = (dout > 0.0f) ? w / dout : 0.0f;
    int q = atomicAdd(&g_cursor[NN + s], 1);
    g_adj_nbr[q]  = d;
    g_adj_coef[q] = (din > 0.0f) ? w / din : 0.0f;
}

// -------- fp16 convert helper: float4 -> 4 packed halves (uint2) --------
__device__ __forceinline__ uint2 cvt4h(float4 v) {
    __half2 H0(__float2half_rn(v.x), __float2half_rn(v.y));
    __half2 H1(__float2half_rn(v.z), __float2half_rn(v.w));
    return make_uint2(*reinterpret_cast<u32*>(&H0), *reinterpret_cast<u32*>(&H1));
}

// -------- k4: fused: CSR gather + X convert + weight convert + state reset --------
__global__ void k_gather(const float* __restrict__ x,
                         const float* __restrict__ Wz, const float* __restrict__ bz,
                         const float* __restrict__ Wh, const float* __restrict__ bh) {
    int gt = blockIdx.x * blockDim.x + threadIdx.x;

    // fused A: reset degree/count state for next replay
    if (gt < 2 * NN) { g_deg[gt] = 0.0f; g_cnt[gt] = 0; }

    // fused B: weights -> transposed fp16 + bias
    if (gt < KC * NC) {
        int k = gt / NC;
        int j = gt % NC;
        const float* W = (j < 128) ? Wz : Wh;
        int jc = j & 127;
        float v;
        if (k < 128)      v = W[k * 128 + jc] + W[(512 + k) * 128 + jc];
        else if (k < 256) v = W[(256 + (k - 128)) * 128 + jc];
        else              v = W[(768 + (k - 256)) * 128 + jc];
        g_Wt[j * KC + k] = __float2half_rn(v);
        if (gt < NC) g_bias[gt] = (gt < 128) ? bz[gt] : bh[gt - 128];
    }

    // fused C: X -> fp16 (one float4 -> uint2 per thread)
    if (gt < MROWS * 32) {
        float4 v = reinterpret_cast<const float4*>(x)[gt];
        reinterpret_cast<uint2*>(g_Xh)[gt] = cvt4h(v);
    }

    // main: CSR gather, one warp per (slot, batch)
    int gw = gt >> 5;
    int lane = threadIdx.x & 31;
    if (gw >= 2 * NN * NB) return;
    int slot = gw >> 2;
    int b    = gw & 3;
    int half = slot / NN;
    int v    = slot % NN;

    int beg = g_off[slot];
    int end = g_off[slot + 1];

    const float4* X4 = reinterpret_cast<const float4*>(x) + (u32)b * (u32)NN * 32u;
    float4 acc = make_float4(0.f, 0.f, 0.f, 0.f);

    int p = beg;
    for (; p + 4 <= end; p += 4) {
        int   n0 = g_adj_nbr[p],     n1 = g_adj_nbr[p + 1];
        int   n2 = g_adj_nbr[p + 2], n3 = g_adj_nbr[p + 3];
        float c0 = g_adj_coef[p],     c1 = g_adj_coef[p + 1];
        float c2 = g_adj_coef[p + 2], c3 = g_adj_coef[p + 3];
        float4 x0 = X4[(u32)n0 * 32u + lane];
        float4 x1 = X4[(u32)n1 * 32u + lane];
        float4 x2 = X4[(u32)n2 * 32u + lane];
        float4 x3 = X4[(u32)n3 * 32u + lane];
        acc.x = fmaf(c0, x0.x, acc.x); acc.y = fmaf(c0, x0.y, acc.y);
        acc.z = fmaf(c0, x0.z, acc.z); acc.w = fmaf(c0, x0.w, acc.w);
        acc.x = fmaf(c1, x1.x, acc.x); acc.y = fmaf(c1, x1.y, acc.y);
        acc.z = fmaf(c1, x1.z, acc.z); acc.w = fmaf(c1, x1.w, acc.w);
        acc.x = fmaf(c2, x2.x, acc.x); acc.y = fmaf(c2, x2.y, acc.y);
        acc.z = fmaf(c2, x2.z, acc.z); acc.w = fmaf(c2, x2.w, acc.w);
        acc.x = fmaf(c3, x3.x, acc.x); acc.y = fmaf(c3, x3.y, acc.y);
        acc.z = fmaf(c3, x3.z, acc.z); acc.w = fmaf(c3, x3.w, acc.w);
    }
    for (; p < end; p++) {
        int   n0 = g_adj_nbr[p];
        float c0 = g_adj_coef[p];
        float4 x0 = X4[(u32)n0 * 32u + lane];
        acc.x = fmaf(c0, x0.x, acc.x); acc.y = fmaf(c0, x0.y, acc.y);
        acc.z = fmaf(c0, x0.z, acc.z); acc.w = fmaf(c0, x0.w, acc.w);
    }

    // g_Th row (b*NN+v): halves [0,128)=Txo (half 0), [128,256)=Txi (half 1)
    u32 idx = (u32)(b * NN + v) * 64u + (u32)half * 32u + (u32)lane;  // uint2 units
    reinterpret_cast<uint2*>(g_Th)[idx] = cvt4h(acc);
}

// -------- k5: cp.async double-buffered fp16 tensor GEMM + fused gate epilogue --------
#define GBM 64
#define GBK 32
#define NITER (KC / GBK)     // 12
#define ASTR 40
#define BSTR 40
#define A_ELEMS (GBM * ASTR)                     // 2560 halves
#define B_ELEMS (NC * BSTR)                      // 10240 halves
#define STAGE_ELEMS (A_ELEMS + B_ELEMS)          // 12800 halves
#define SMEM_BYTES (2 * STAGE_ELEMS * 2)         // 51200 B

#define MMA_F16(c, a0, a1, a2, a3, b0, b1)                                 \
    asm("mma.sync.aligned.m16n8k16.row.col.f32.f16.f16.f32 "               \
        "{%0,%1,%2,%3}, {%4,%5,%6,%7}, {%8,%9}, {%0,%1,%2,%3};"            \
        : "+f"((c)[0]), "+f"((c)[1]), "+f"((c)[2]), "+f"((c)[3])           \
        : "r"(a0), "r"(a1), "r"(a2), "r"(a3), "r"(b0), "r"(b1))

__device__ __forceinline__ void cpa16(__half* dst, const __half* src) {
    u32 d = (u32)__cvta_generic_to_shared(dst);
    asm volatile("cp.async.cg.shared.global [%0], [%1], 16;" :: "r"(d), "l"(src));
}

__device__ __forceinline__ void issue_stage(__half* sm, int stage, int k0,
                                            int bm, int tid) {
    __half* As = sm + stage * STAGE_ELEMS;
    __half* Bs = As + A_ELEMS;
    // A: 256 16B-chunks, 1 per thread. chunk c: row=c>>2, q=c&3
    {
        int rr = tid >> 2;
        int q  = tid & 3;
        const __half* src;
        if (k0 < 128)
            src = g_Xh + (size_t)(bm + rr) * 128 + k0 + q * 8;
        else
            src = g_Th + (size_t)(bm + rr) * 256 + (k0 - 128) + q * 8;
        cpa16(As + rr * ASTR + q * 8, src);
    }
    // B: 1024 chunks, 4 per thread. chunk c: n=c>>2, q=c&3
    #pragma unroll
    for (int j = 0; j < 4; j++) {
        int c = tid + j * 256;
        int n = c >> 2;
        int q = c & 3;
        cpa16(Bs + n * BSTR + q * 8, g_Wt + n * KC + k0 + q * 8);
    }
    asm volatile("cp.async.commit_group;");
}

__global__ void __launch_bounds__(256) k_gemm(float* __restrict__ out) {
    extern __shared__ __align__(16) __half sm[];
    int tid = threadIdx.x;
    int w = tid >> 5, lane = tid & 31;
    int g = lane >> 2, t = lane & 3;
    int bm = blockIdx.x * GBM;

    float acc[4][2][2][4];
    #pragma unroll
    for (int mi = 0; mi < 4; mi++)
        #pragma unroll
        for (int zh = 0; zh < 2; zh++)
            #pragma unroll
            for (int nj = 0; nj < 2; nj++)
                #pragma unroll
                for (int q = 0; q < 4; q++) acc[mi][zh][nj][q] = 0.f;

    issue_stage(sm, 0, 0, bm, tid);

    for (int it = 0; it < NITER; it++) {
        if (it + 1 < NITER) {
            issue_stage(sm, (it + 1) & 1, (it + 1) * GBK, bm, tid);
            asm volatile("cp.async.wait_group 1;");
        } else {
            asm volatile("cp.async.wait_group 0;");
        }
        __syncthreads();

        const __half* As = sm + (it & 1) * STAGE_ELEMS;
        const __half* Bs = As + A_ELEMS;

        #pragma unroll
        for (int ks = 0; ks < 2; ks++) {
            int kk = ks * 16 + 2 * t;
            u32 bf[2][2][2];
            #pragma unroll
            for (int zh = 0; zh < 2; zh++)
                #pragma unroll
                for (int nj = 0; nj < 2; nj++) {
                    int n = w * 16 + nj * 8 + g + zh * 128;
                    bf[zh][nj][0] = *reinterpret_cast<const u32*>(&Bs[n * BSTR + kk]);
                    bf[zh][nj][1] = *reinterpret_cast<const u32*>(&Bs[n * BSTR + kk + 8]);
                }
            #pragma unroll
            for (int mi = 0; mi < 4; mi++) {
                int r = mi * 16 + g;
                u32 a0 = *reinterpret_cast<const u32*>(&As[r * ASTR + kk]);
                u32 a1 = *reinterpret_cast<const u32*>(&As[(r + 8) * ASTR + kk]);
                u32 a2 = *reinterpret_cast<const u32*>(&As[r * ASTR + kk + 8]);
                u32 a3 = *reinterpret_cast<const u32*>(&As[(r + 8) * ASTR + kk + 8]);
                #pragma unroll
                for (int zh = 0; zh < 2; zh++)
                    #pragma unroll
                    for (int nj = 0; nj < 2; nj++)
                        MMA_F16(acc[mi][zh][nj], a0, a1, a2, a3,
                                bf[zh][nj][0], bf[zh][nj][1]);
            }
        }
        __syncthreads();
    }

    // ---- fused gate epilogue ----
    #pragma unroll
    for (int nj = 0; nj < 2; nj++) {
        int col = w * 16 + nj * 8 + 2 * t;
        float bz0 = g_bias[col],       bz1 = g_bias[col + 1];
        float bh0 = g_bias[128 + col], bh1 = g_bias[129 + col];
        #pragma unroll
        for (int mi = 0; mi < 4; mi++) {
            int r0 = bm + mi * 16 + g;
            float* z = acc[mi][0][nj];
            float* h = acc[mi][1][nj];
            if (r0 < MROWS) {
                float2 o;
                o.x = (1.0f / (1.0f + expf(z[0] + bz0))) * tanhf(h[0] + bh0);
                o.y = (1.0f / (1.0f + expf(z[1] + bz1))) * tanhf(h[1] + bh1);
                *reinterpret_cast<float2*>(&out[(size_t)r0 * 128 + col]) = o;
            }
            int r1 = r0 + 8;
            if (r1 < MROWS) {
                float2 o;
                o.x = (1.0f / (1.0f + expf(z[2] + bz0))) * tanhf(h[2] + bh0);
                o.y = (1.0f / (1.0f + expf(z[3] + bz1))) * tanhf(h[3] + bh1);
                *reinterpret_cast<float2*>(&out[(size_t)r1 * 128 + col]) = o;
            }
        }
    }
}

extern "C" void kernel_launch(void* const* d_in, const int* in_sizes, int n_in,
                              void* d_out, int out_size) {
    const float* x  = (const float*)d_in[0];
    const int*   ei = (const int*)d_in[1];
    const float* ew = (const float*)d_in[2];
    const float* Wz = (const float*)d_in[3];
    const float* bz = (const float*)d_in[4];
    // d_in[5]=Wr, d_in[6]=br : dead (H0 == 0 => R multiplies zero)
    const float* Wh = (const float*)d_in[7];
    const float* bh = (const float*)d_in[8];
    float* out = (float*)d_out;

    cudaFuncSetAttribute(k_gemm, cudaFuncAttributeMaxDynamicSharedMemorySize, SMEM_BYTES);

    k_degcnt <<<(NE + 255) / 256, 256>>>(ei, ew);                          // #1
    k_scan   <<<1, 1024>>>();                                              // #2
    k_fill   <<<(NE + 255) / 256, 256>>>(ei, ew);                          // #3
    k_gather <<<(2 * NN * NB * 32 + 255) / 256, 256>>>(x, Wz, bz, Wh, bh); // #4
    k_gemm   <<<MPAD / GBM, 256, SMEM_BYTES>>>(out);                       // #5
}

// round 13
// speedup vs baseline: 3.1762x; 1.0369x over previous
#include <cuda_runtime.h>
#include <cuda_fp16.h>
#include <math.h>

// Problem constants (fixed shapes)
#define NB    4
#define NN    5000
#define NE    80000
#define MROWS 20000
#define MPAD  20096     // 314*64
#define KC    384       // [X | Txo | Txi]
#define NC    256       // [z | h]
#define SCAN_N (2*NN)

typedef unsigned int u32;

// -------- device scratch (static; zero-initialized at module load) --------
__device__ __align__(16) __half g_Xh[(size_t)MPAD * 128];   // X fp16; pad rows stay 0
__device__ __align__(16) __half g_Th[(size_t)MPAD * 256];   // [Txo|Txi] fp16; pad rows stay 0
__device__ __align__(16) __half g_Wt[NC * KC];              // Wcat^T [n][k] fp16
__device__ __align__(16) float g_bias[NC];
__device__ float g_deg[2 * NN];
__device__ int   g_cnt[SCAN_N];
__device__ int   g_off[SCAN_N + 1];
__device__ int   g_cursor[SCAN_N];
__device__ __align__(8) int2 g_adj[2 * NE];   // (nbr, coef-as-int) per CSR slot

// -------- fp16 convert helper: float4 -> 4 packed halves (uint2) --------
__device__ __forceinline__ uint2 cvt4h(float4 v) {
    __half2 H0(__float2half_rn(v.x), __float2half_rn(v.y));
    __half2 H1(__float2half_rn(v.z), __float2half_rn(v.w));
    return make_uint2(*reinterpret_cast<u32*>(&H0), *reinterpret_cast<u32*>(&H1));
}

// -------- k1: degrees/counts (split src/dst sides) + X -> fp16 convert --------
__global__ void k_degcnt(const int* __restrict__ ei, const float* __restrict__ ew,
                         const float* __restrict__ x) {
    int gt = blockIdx.x * blockDim.x + threadIdx.x;
    if (gt < 2 * NE) {
        if (gt < NE) {                       // src side
            int s = ei[gt];
            float w = ew[gt];
            atomicAdd(&g_deg[s], w);         // weighted out-degree
            atomicAdd(&g_cnt[NN + s], 1);    // out-count (Txi CSR)
        } else {                             // dst side
            int e = gt - NE;
            int d = ei[NE + e];
            float w = ew[e];
            atomicAdd(&g_deg[NN + d], w);    // weighted in-degree
            atomicAdd(&g_cnt[d], 1);         // in-count (Txo CSR)
        }
    }
    // fused: X -> fp16 (one float4 -> uint2 per thread)
    if (gt < MROWS * 32) {
        float4 v = reinterpret_cast<const float4*>(x)[gt];
        reinterpret_cast<uint2*>(g_Xh)[gt] = cvt4h(v);
    }
}

// -------- k2: exclusive scan via warp shuffles --------
__global__ void __launch_bounds__(1024) k_scan() {
    __shared__ int warp_sums[32];
    const int PER = 10;
    int t = threadIdx.x;
    int lane = t & 31, wid = t >> 5;
    int base = t * PER;
    int local[PER];
    int s = 0;
    #pragma unroll
    for (int i = 0; i < PER; i++) {
        int idx = base + i;
        int v = (idx < SCAN_N) ? g_cnt[idx] : 0;
        local[i] = s; s += v;
    }
    int sc = s;
    #pragma unroll
    for (int o = 1; o < 32; o <<= 1) {
        int u = __shfl_up_sync(0xFFFFFFFFu, sc, o);
        if (lane >= o) sc += u;
    }
    if (lane == 31) warp_sums[wid] = sc;
    __syncthreads();
    if (wid == 0) {
        int ws = warp_sums[lane];
        #pragma unroll
        for (int o = 1; o < 32; o <<= 1) {
            int u = __shfl_up_sync(0xFFFFFFFFu, ws, o);
            if (lane >= o) ws += u;
        }
        warp_sums[lane] = ws;
    }
    __syncthreads();
    int carry = (sc - s) + (wid > 0 ? warp_sums[wid - 1] : 0);
    #pragma unroll
    for (int i = 0; i < PER; i++) {
        int idx = base + i;
        if (idx < SCAN_N) {
            int o = carry + local[i];
            g_off[idx] = o;
            g_cursor[idx] = o;
        }
    }
    if (t == 1023) g_off[SCAN_N] = carry + s;
}

// -------- k3: fill adjacency (split: one CSR entry per thread) --------
__global__ void k_fill(const int* __restrict__ ei, const float* __restrict__ ew) {
    int gt = blockIdx.x * blockDim.x + threadIdx.x;
    if (gt >= 2 * NE) return;
    if (gt < NE) {                            // in-CSR entry of dst (Txo)
        int e = gt;
        int s = ei[e], d = ei[NE + e];
        float w = ew[e];
        float dout = g_deg[s];
        float co = (dout > 0.0f) ? w / dout : 0.0f;
        int p = atomicAdd(&g_cursor[d], 1);
        g_adj[p] = make_int2(s, __float_as_int(co));
    } else {                                  // out-CSR entry of src (Txi)
        int e = gt - NE;
        int s = ei[e], d = ei[NE + e];
        float w = ew[e];
        float din = g_deg[NN + d];
        float ci = (din > 0.0f) ? w / din : 0.0f;
        int q = atomicAdd(&g_cursor[NN + s], 1);
        g_adj[q] = make_int2(d, __float_as_int(ci));
    }
}

// -------- fp16-read fma: acc += c * (4 halves) --------
__device__ __forceinline__ void fma_h4(float4& acc, float c, uint2 u) {
    float2 f0 = __half22float2(*reinterpret_cast<__half2*>(&u.x));
    float2 f1 = __half22float2(*reinterpret_cast<__half2*>(&u.y));
    acc.x = fmaf(c, f0.x, acc.x);
    acc.y = fmaf(c, f0.y, acc.y);
    acc.z = fmaf(c, f1.x, acc.z);
    acc.w = fmaf(c, f1.y, acc.w);
}

// -------- k4: fused: CSR gather (fp16 reads) + weight convert + state reset --------
__global__ void k_gather(const float* __restrict__ Wz, const float* __restrict__ bz,
                         const float* __restrict__ Wh, const float* __restrict__ bh) {
    int gt = blockIdx.x * blockDim.x + threadIdx.x;

    // fused A: reset degree/count state for next replay
    if (gt < 2 * NN) { g_deg[gt] = 0.0f; g_cnt[gt] = 0; }

    // fused B: weights -> transposed fp16 + bias
    if (gt < KC * NC) {
        int k = gt / NC;
        int j = gt % NC;
        const float* W = (j < 128) ? Wz : Wh;
        int jc = j & 127;
        float v;
        if (k < 128)      v = W[k * 128 + jc] + W[(512 + k) * 128 + jc];
        else if (k < 256) v = W[(256 + (k - 128)) * 128 + jc];
        else              v = W[(768 + (k - 256)) * 128 + jc];
        g_Wt[j * KC + k] = __float2half_rn(v);
        if (gt < NC) g_bias[gt] = (gt < 128) ? bz[gt] : bh[gt - 128];
    }

    // main: CSR gather, one warp per (slot, batch)
    int gw = gt >> 5;
    int lane = threadIdx.x & 31;
    if (gw >= 2 * NN * NB) return;
    int slot = gw >> 2;
    int b    = gw & 3;
    int half = slot / NN;
    int v    = slot % NN;

    int beg = g_off[slot];
    int end = g_off[slot + 1];

    const uint2* X2 = reinterpret_cast<const uint2*>(g_Xh) + (u32)b * (u32)NN * 32u;
    float4 acc = make_float4(0.f, 0.f, 0.f, 0.f);

    int p = beg;
    for (; p + 4 <= end; p += 4) {
        int2 a0 = g_adj[p],     a1 = g_adj[p + 1];
        int2 a2 = g_adj[p + 2], a3 = g_adj[p + 3];
        uint2 u0 = X2[(u32)a0.x * 32u + lane];
        uint2 u1 = X2[(u32)a1.x * 32u + lane];
        uint2 u2 = X2[(u32)a2.x * 32u + lane];
        uint2 u3 = X2[(u32)a3.x * 32u + lane];
        fma_h4(acc, __int_as_float(a0.y), u0);
        fma_h4(acc, __int_as_float(a1.y), u1);
        fma_h4(acc, __int_as_float(a2.y), u2);
        fma_h4(acc, __int_as_float(a3.y), u3);
    }
    for (; p < end; p++) {
        int2 a0 = g_adj[p];
        uint2 u0 = X2[(u32)a0.x * 32u + lane];
        fma_h4(acc, __int_as_float(a0.y), u0);
    }

    // g_Th row (b*NN+v): halves [0,128)=Txo (half 0), [128,256)=Txi (half 1)
    u32 idx = (u32)(b * NN + v) * 64u + (u32)half * 32u + (u32)lane;  // uint2 units
    reinterpret_cast<uint2*>(g_Th)[idx] = cvt4h(acc);
}

// -------- k5: cp.async double-buffered fp16 tensor GEMM + fused gate epilogue --------
#define GBM 64
#define GBK 32
#define NITER (KC / GBK)     // 12
#define ASTR 40
#define BSTR 40
#define A_ELEMS (GBM * ASTR)                     // 2560 halves
#define B_ELEMS (NC * BSTR)                      // 10240 halves
#define STAGE_ELEMS (A_ELEMS + B_ELEMS)          // 12800 halves
#define SMEM_BYTES (2 * STAGE_ELEMS * 2)         // 51200 B

#define MMA_F16(c, a0, a1, a2, a3, b0, b1)                                 \
    asm("mma.sync.aligned.m16n8k16.row.col.f32.f16.f16.f32 "               \
        "{%0,%1,%2,%3}, {%4,%5,%6,%7}, {%8,%9}, {%0,%1,%2,%3};"            \
        : "+f"((c)[0]), "+f"((c)[1]), "+f"((c)[2]), "+f"((c)[3])           \
        : "r"(a0), "r"(a1), "r"(a2), "r"(a3), "r"(b0), "r"(b1))

__device__ __forceinline__ void cpa16(__half* dst, const __half* src) {
    u32 d = (u32)__cvta_generic_to_shared(dst);
    asm volatile("cp.async.cg.shared.global [%0], [%1], 16;" :: "r"(d), "l"(src));
}

__device__ __forceinline__ void issue_stage(__half* sm, int stage, int k0,
                                            int bm, int tid) {
    __half* As = sm + stage * STAGE_ELEMS;
    __half* Bs = As + A_ELEMS;
    // A: 256 16B-chunks, 1 per thread. chunk c: row=c>>2, q=c&3
    {
        int rr = tid >> 2;
        int q  = tid & 3;
        const __half* src;
        if (k0 < 128)
            src = g_Xh + (size_t)(bm + rr) * 128 + k0 + q * 8;
        else
            src = g_Th + (size_t)(bm + rr) * 256 + (k0 - 128) + q * 8;
        cpa16(As + rr * ASTR + q * 8, src);
    }
    // B: 1024 chunks, 4 per thread. chunk c: n=c>>2, q=c&3
    #pragma unroll
    for (int j = 0; j < 4; j++) {
        int c = tid + j * 256;
        int n = c >> 2;
        int q = c & 3;
        cpa16(Bs + n * BSTR + q * 8, g_Wt + n * KC + k0 + q * 8);
    }
    asm volatile("cp.async.commit_group;");
}

__global__ void __launch_bounds__(256) k_gemm(float* __restrict__ out) {
    extern __shared__ __align__(16) __half sm[];
    int tid = threadIdx.x;
    int w = tid >> 5, lane = tid & 31;
    int g = lane >> 2, t = lane & 3;
    int bm = blockIdx.x * GBM;

    float acc[4][2][2][4];
    #pragma unroll
    for (int mi = 0; mi < 4; mi++)
        #pragma unroll
        for (int zh = 0; zh < 2; zh++)
            #pragma unroll
            for (int nj = 0; nj < 2; nj++)
                #pragma unroll
                for (int q = 0; q < 4; q++) acc[mi][zh][nj][q] = 0.f;

    issue_stage(sm, 0, 0, bm, tid);

    for (int it = 0; it < NITER; it++) {
        if (it + 1 < NITER) {
            issue_stage(sm, (it + 1) & 1, (it + 1) * GBK, bm, tid);
            asm volatile("cp.async.wait_group 1;");
        } else {
            asm volatile("cp.async.wait_group 0;");
        }
        __syncthreads();

        const __half* As = sm + (it & 1) * STAGE_ELEMS;
        const __half* Bs = As + A_ELEMS;

        #pragma unroll
        for (int ks = 0; ks < 2; ks++) {
            int kk = ks * 16 + 2 * t;
            u32 bf[2][2][2];
            #pragma unroll
            for (int zh = 0; zh < 2; zh++)
                #pragma unroll
                for (int nj = 0; nj < 2; nj++) {
                    int n = w * 16 + nj * 8 + g + zh * 128;
                    bf[zh][nj][0] = *reinterpret_cast<const u32*>(&Bs[n * BSTR + kk]);
                    bf[zh][nj][1] = *reinterpret_cast<const u32*>(&Bs[n * BSTR + kk + 8]);
                }
            #pragma unroll
            for (int mi = 0; mi < 4; mi++) {
                int r = mi * 16 + g;
                u32 a0 = *reinterpret_cast<const u32*>(&As[r * ASTR + kk]);
                u32 a1 = *reinterpret_cast<const u32*>(&As[(r + 8) * ASTR + kk]);
                u32 a2 = *reinterpret_cast<const u32*>(&As[r * ASTR + kk + 8]);
                u32 a3 = *reinterpret_cast<const u32*>(&As[(r + 8) * ASTR + kk + 8]);
                #pragma unroll
                for (int zh = 0; zh < 2; zh++)
                    #pragma unroll
                    for (int nj = 0; nj < 2; nj++)
                        MMA_F16(acc[mi][zh][nj], a0, a1, a2, a3,
                                bf[zh][nj][0], bf[zh][nj][1]);
            }
        }
        __syncthreads();
    }

    // ---- fused gate epilogue ----
    #pragma unroll
    for (int nj = 0; nj < 2; nj++) {
        int col = w * 16 + nj * 8 + 2 * t;
        float bz0 = g_bias[col],       bz1 = g_bias[col + 1];
        float bh0 = g_bias[128 + col], bh1 = g_bias[129 + col];
        #pragma unroll
        for (int mi = 0; mi < 4; mi++) {
            int r0 = bm + mi * 16 + g;
            float* z = acc[mi][0][nj];
            float* h = acc[mi][1][nj];
            if (r0 < MROWS) {
                float2 o;
                o.x = (1.0f / (1.0f + expf(z[0] + bz0))) * tanhf(h[0] + bh0);
                o.y = (1.0f / (1.0f + expf(z[1] + bz1))) * tanhf(h[1] + bh1);
                *reinterpret_cast<float2*>(&out[(size_t)r0 * 128 + col]) = o;
            }
            int r1 = r0 + 8;
            if (r1 < MROWS) {
                float2 o;
                o.x = (1.0f / (1.0f + expf(z[2] + bz0))) * tanhf(h[2] + bh0);
                o.y = (1.0f / (1.0f + expf(z[3] + bz1))) * tanhf(h[3] + bh1);
                *reinterpret_cast<float2*>(&out[(size_t)r1 * 128 + col]) = o;
            }
        }
    }
}

extern "C" void kernel_launch(void* const* d_in, const int* in_sizes, int n_in,
                              void* d_out, int out_size) {
    const float* x  = (const float*)d_in[0];
    const int*   ei = (const int*)d_in[1];
    const float* ew = (const float*)d_in[2];
    const float* Wz = (const float*)d_in[3];
    const float* bz = (const float*)d_in[4];
    // d_in[5]=Wr, d_in[6]=br : dead (H0 == 0 => R multiplies zero)
    const float* Wh = (const float*)d_in[7];
    const float* bh = (const float*)d_in[8];
    float* out = (float*)d_out;

    cudaFuncSetAttribute(k_gemm, cudaFuncAttributeMaxDynamicSharedMemorySize, SMEM_BYTES);

    k_degcnt <<<(MROWS * 32 + 255) / 256, 256>>>(ei, ew, x);            // #1 (640K thr)
    k_scan   <<<1, 1024>>>();                                           // #2
    k_fill   <<<(2 * NE + 255) / 256, 256>>>(ei, ew);                   // #3
    k_gather <<<(2 * NN * NB * 32 + 255) / 256, 256>>>(Wz, bz, Wh, bh); // #4
    k_gemm   <<<MPAD / GBM, 256, SMEM_BYTES>>>(out);                    // #5
}